// round 7
// baseline (speedup 1.0000x reference)
#include <cuda_runtime.h>
#include <cstdint>

#define ND 4096
#define KD 2048                 // folded K
#define BM 128
#define BN 128
#define BK 32
#define STAGES 3
#define KITERS (KD / BK)        // 64

#define STAGE_BYTES ((BM + BN) * BK * 4)          // 32 KB
#define SMEM_TOTAL (STAGES * STAGE_BYTES)         // 96 KB -> 2 CTAs/SM

// Scratch (device globals are the sanctioned scratch; no cudaMalloc).
__device__ __align__(1024) float g_Ce[(size_t)KD * KD];   // C[2v][j]
__device__ __align__(1024) float g_Co[(size_t)KD * KD];   // C[2v+1][j]
__device__ __align__(1024) float g_Xs[(size_t)ND * KD];
__device__ __align__(1024) float g_Xa[(size_t)ND * KD];
__device__ __align__(1024) float g_Yt[(size_t)ND * ND];
__device__ __align__(1024) float g_Ys[(size_t)ND * KD];
__device__ __align__(1024) float g_Ya[(size_t)ND * KD];

// ---------------------------------------------------------------- helpers
__device__ __forceinline__ uint32_t smem_u32(const void* p) {
    uint32_t a;
    asm("{ .reg .u64 t; cvta.to.shared.u64 t, %1; cvt.u32.u64 %0, t; }"
        : "=r"(a) : "l"(p));
    return a;
}
__device__ __forceinline__ float tf32_rna(float x) {
    uint32_t b;
    asm("cvt.rna.tf32.f32 %0, %1;" : "=r"(b) : "f"(x));
    return __uint_as_float(b);
}
__device__ __forceinline__ uint32_t swz(uint32_t off) {
    return off ^ ((off >> 3) & 0x70);  // SW128 (Swizzle<3,4,3>), 128B rows
}
__device__ __forceinline__ void cp16(uint32_t sdst, const float* gsrc) {
    asm volatile("cp.async.cg.shared.global [%0], [%1], 16;"
                 :: "r"(sdst), "l"(__cvta_generic_to_global(gsrc)) : "memory");
}
__device__ __forceinline__ void cp_commit() {
    asm volatile("cp.async.commit_group;" ::: "memory");
}
template <int N>
__device__ __forceinline__ void cp_wait() {
    asm volatile("cp.async.wait_group %0;" :: "n"(N) : "memory");
}
__device__ __forceinline__ void ldsm4(uint32_t* r, uint32_t a) {
    asm volatile("ldmatrix.sync.aligned.m8n8.x4.shared.b16 {%0,%1,%2,%3}, [%4];"
                 : "=r"(r[0]), "=r"(r[1]), "=r"(r[2]), "=r"(r[3]) : "r"(a));
}
__device__ __forceinline__ void mma1688(float* d, const uint32_t* a, const uint32_t* b) {
    asm volatile(
        "mma.sync.aligned.m16n8k8.row.col.f32.tf32.tf32.f32 "
        "{%0,%1,%2,%3}, {%4,%5,%6,%7}, {%8,%9}, {%0,%1,%2,%3};"
        : "+f"(d[0]), "+f"(d[1]), "+f"(d[2]), "+f"(d[3])
        : "r"(a[0]), "r"(a[1]), "r"(a[2]), "r"(a[3]), "r"(b[0]), "r"(b[1]));
}

// ---------------------------------------------------------------- basis
__global__ void gen_c_kernel(float4* __restrict__ Ce4, float4* __restrict__ Co4) {
    int v  = blockIdx.y;
    int q  = blockIdx.x * blockDim.x + threadIdx.x;
    int j0 = q << 2;
    const float s = 1.0f / 8192.0f;
    int ke = 2 * v, ko = 2 * v + 1;
    int be = (2 * j0 + 1) * ke, se = 2 * ke;
    int bo = (2 * j0 + 1) * ko, so = 2 * ko;
    float4 re, ro;
    re.x = tf32_rna(cospif((float)((be         ) & 16383) * s));
    re.y = tf32_rna(cospif((float)((be +     se) & 16383) * s));
    re.z = tf32_rna(cospif((float)((be + 2 * se) & 16383) * s));
    re.w = tf32_rna(cospif((float)((be + 3 * se) & 16383) * s));
    ro.x = tf32_rna(cospif((float)((bo         ) & 16383) * s));
    ro.y = tf32_rna(cospif((float)((bo +     so) & 16383) * s));
    ro.z = tf32_rna(cospif((float)((bo + 2 * so) & 16383) * s));
    ro.w = tf32_rna(cospif((float)((bo + 3 * so) & 16383) * s));
    Ce4[(size_t)v * (KD / 4) + q] = re;
    Co4[(size_t)v * (KD / 4) + q] = ro;
}

// Fold rows of length ND into sum/diff halves of length KD, tf32-rounded.
__global__ void fold_kernel(const float* __restrict__ src,
                            float* __restrict__ s_out, float* __restrict__ a_out) {
    const int qpr = KD / 4;
    const size_t total = (size_t)ND * qpr;
    for (size_t idx = blockIdx.x * blockDim.x + threadIdx.x; idx < total;
         idx += (size_t)gridDim.x * blockDim.x) {
        size_t row = idx / qpr;
        int q = (int)(idx % qpr);
        const float* rp = src + row * ND;
        float4 f  = *(const float4*)&rp[q * 4];
        float4 rv = *(const float4*)&rp[ND - 4 - q * 4];
        float4 sv, av;
        sv.x = tf32_rna(f.x + rv.w);  av.x = tf32_rna(f.x - rv.w);
        sv.y = tf32_rna(f.y + rv.z);  av.y = tf32_rna(f.y - rv.z);
        sv.z = tf32_rna(f.z + rv.y);  av.z = tf32_rna(f.z - rv.y);
        sv.w = tf32_rna(f.w + rv.x);  av.w = tf32_rna(f.w - rv.x);
        *(float4*)&s_out[row * KD + q * 4] = sv;
        *(float4*)&a_out[row * KD + q * 4] = av;
    }
}

// ---------------------------------------------------------------- GEMM
// D[m,n] = sum_k A[m,k]*B[n,k], K = KD.  nb<16 -> even parity, else odd.
// Transposed store: outT[2*n+par][m].
// 128 threads = 4 warps (2x2), warp tile 64x64, CTA tile 128x128.
// Fragment pipeline: B single-buffered per ks, A double-buffered (next ks
// prefetched during current MMAs; volatile asm preserves program order).
__global__ void __launch_bounds__(128, 2) dct_gemm_kernel(
    const float* __restrict__ Ae, const float* __restrict__ Ao,
    const float* __restrict__ Be, const float* __restrict__ Bo,
    float* __restrict__ outT)
{
    extern __shared__ __align__(1024) char smem[];
    uint32_t sb = smem_u32(smem);
    int tid = threadIdx.x;
    int wid = tid >> 5, lane = tid & 31;
    int mb = blockIdx.x;
    int nb = blockIdx.y;
    int par = nb >> 4;
    int nbe = nb & 15;
    const float* A = par ? Ao : Ae;
    const float* B = par ? Bo : Be;

    // cp.async: 128 threads cover 16 rows x 8 chunks per pass; 8 passes/tile.
    int crow = tid >> 3, cch = tid & 7;
    const float* Ag = A + (size_t)(mb * BM + crow) * KD + cch * 4;
    const float* Bg = B + (size_t)(nbe * BN + crow) * KD + cch * 4;
    uint32_t sA = swz((uint32_t)(crow * 128 + cch * 16));

    auto issue_stage = [&](int k, int s) {
        uint32_t Ab = sb + s * STAGE_BYTES;
        uint32_t Bb = Ab + BM * 128;
        const float* ga = Ag + k * BK;
        const float* gb = Bg + k * BK;
        #pragma unroll
        for (int t = 0; t < 8; t++) {
            uint32_t so = sA + t * 16 * 128;
            cp16(Ab + so, ga + (size_t)(t * 16) * KD);
            cp16(Bb + so, gb + (size_t)(t * 16) * KD);
        }
    };

    #pragma unroll
    for (int s = 0; s < STAGES - 1; s++) {
        issue_stage(s, s);
        cp_commit();
    }

    // warp grid: 2 (m) x 2 (n); warp tile 64 x 64
    int WM = (wid >> 1) * 64;
    int WN = (wid & 1) * 64;

    float d[4][8][4];
    #pragma unroll
    for (int mt = 0; mt < 4; mt++)
        #pragma unroll
        for (int nt = 0; nt < 8; nt++)
            #pragma unroll
            for (int j = 0; j < 4; j++) d[mt][nt][j] = 0.0f;

    uint32_t aoff = (uint32_t)((lane & 15) * 128 + (lane >> 4) * 16);
    uint32_t boff = (uint32_t)(((lane & 7) + ((lane >> 4) << 3)) * 128
                               + ((lane >> 3) & 1) * 16);

    uint32_t a[2][4][4];   // double-buffered A frags
    uint32_t bfr[4][4];    // B frags for current ks

    int s = 0;
    for (int k = 0; k < KITERS; k++) {
        cp_wait<STAGES - 2>();       // stage-k data arrived (this thread)
        __syncthreads();             // visible to all; stage k-1 fully consumed
        if (k + STAGES - 1 < KITERS)
            issue_stage(k + STAGES - 1, (k + STAGES - 1) % STAGES);
        cp_commit();                 // empty commits at tail keep count uniform

        uint32_t Ab = sb + s * STAGE_BYTES;
        uint32_t Bb = Ab + BM * 128;

        // preload A frags for ks=0
        #pragma unroll
        for (int q = 0; q < 4; q++)
            ldsm4(a[0][q], Ab + swz((uint32_t)((WM + q * 16) * 128) + aoff));

        #pragma unroll
        for (int ks = 0; ks < 4; ks++) {
            int cur = ks & 1, nxt = cur ^ 1;
            // B frags for current ks
            #pragma unroll
            for (int p = 0; p < 4; p++)
                ldsm4(bfr[p], Bb + swz((uint32_t)((WN + p * 16) * 128) + boff + ks * 32));
            // prefetch A frags for next ks (overlaps with MMAs below)
            if (ks < 3) {
                #pragma unroll
                for (int q = 0; q < 4; q++)
                    ldsm4(a[nxt][q],
                          Ab + swz((uint32_t)((WM + q * 16) * 128) + aoff + (ks + 1) * 32));
            }
            #pragma unroll
            for (int nt = 0; nt < 8; nt++) {
                const uint32_t* bb = &bfr[nt >> 1][(nt & 1) * 2];
                #pragma unroll
                for (int mt = 0; mt < 4; mt++)
                    mma1688(d[mt][nt], a[cur][mt], bb);
            }
        }
        s = (s == STAGES - 1) ? 0 : s + 1;
    }

    // -------- epilogue: transpose through SMEM, coalesced float4 stores
    cp_wait<0>();
    __syncthreads();
    float* T = (float*)smem;  // [128][132] = 67.6KB <= 96KB
    int g = lane >> 2, tig = lane & 3;
    #pragma unroll
    for (int mt = 0; mt < 4; mt++) {
        #pragma unroll
        for (int nt = 0; nt < 8; nt++) {
            int m = WM + mt * 16 + g;
            int n = WN + nt * 8 + 2 * tig;
            T[n * 132 + m]           = d[mt][nt][0];
            T[(n + 1) * 132 + m]     = d[mt][nt][1];
            T[n * 132 + m + 8]       = d[mt][nt][2];
            T[(n + 1) * 132 + m + 8] = d[mt][nt][3];
        }
    }
    __syncthreads();
    #pragma unroll
    for (int it = 0; it < 32; it++) {
        int i = tid + it * 128;
        int r = i >> 5, c = (i & 31) * 4;
        float4 v = *(float4*)&T[r * 132 + c];
        size_t orow = (size_t)(2 * (nbe * BN + r) + par);
        *(float4*)&outT[orow * ND + mb * BM + c] = v;
    }
}

// ---------------------------------------------------------------- host
extern "C" void kernel_launch(void* const* d_in, const int* in_sizes, int n_in,
                              void* d_out, int out_size) {
    void *pCe, *pCo, *pXs, *pXa, *pYt, *pYs, *pYa;
    cudaGetSymbolAddress(&pCe, g_Ce);
    cudaGetSymbolAddress(&pCo, g_Co);
    cudaGetSymbolAddress(&pXs, g_Xs);
    cudaGetSymbolAddress(&pXa, g_Xa);
    cudaGetSymbolAddress(&pYt, g_Yt);
    cudaGetSymbolAddress(&pYs, g_Ys);
    cudaGetSymbolAddress(&pYa, g_Ya);

    gen_c_kernel<<<dim3(2, KD), 256>>>((float4*)pCe, (float4*)pCo);
    fold_kernel<<<2048, 256>>>((const float*)d_in[0], (float*)pXs, (float*)pXa);

    cudaFuncSetAttribute(dct_gemm_kernel,
                         cudaFuncAttributeMaxDynamicSharedMemorySize, SMEM_TOTAL);

    // Pass A: Y[i,v]; even v from (Xs,Ce), odd v from (Xa,Co) -> Yt[v][i]
    dct_gemm_kernel<<<dim3(ND / BM, 2 * KD / BN), 128, SMEM_TOTAL>>>(
        (const float*)pXs, (const float*)pXa,
        (const float*)pCe, (const float*)pCo, (float*)pYt);

    // Fold Yt along i for pass B
    fold_kernel<<<2048, 256>>>((const float*)pYt, (float*)pYs, (float*)pYa);

    // Pass B: out[u][v]; even u from (Ys,Ce), odd u from (Ya,Co)
    dct_gemm_kernel<<<dim3(ND / BM, 2 * KD / BN), 128, SMEM_TOTAL>>>(
        (const float*)pYs, (const float*)pYa,
        (const float*)pCe, (const float*)pCo, (float*)d_out);
}

// round 8
// speedup vs baseline: 1.2939x; 1.2939x over previous
#include <cuda_runtime.h>
#include <cstdint>

#define ND 4096
#define BM 128
#define BN 128
#define BK 32
#define STAGES 3

#define STAGE_BYTES ((BM + BN) * BK * 4)          // 32 KB
#define SMEM_TOTAL (STAGES * STAGE_BYTES)         // 96 KB -> 2 CTAs/SM

// Scratch (device globals are the sanctioned scratch; no cudaMalloc).
__device__ __align__(1024) float g_Co [(size_t)2048 * 2048];  // C[2t+1][j], j<2048
__device__ __align__(1024) float g_Cee[(size_t)1024 * 1024];  // cos(pi(2j+1)w/2048)
__device__ __align__(1024) float g_Ceo[(size_t)1024 * 1024];  // cos(pi(2j+1)(2w+1)/4096)
__device__ __align__(1024) float g_Xs [(size_t)ND * 2048];
__device__ __align__(1024) float g_Xa [(size_t)ND * 2048];
__device__ __align__(1024) float g_Xss[(size_t)ND * 1024];
__device__ __align__(1024) float g_Xsa[(size_t)ND * 1024];
__device__ __align__(1024) float g_Yt [(size_t)ND * ND];
__device__ __align__(1024) float g_Ys [(size_t)ND * 2048];
__device__ __align__(1024) float g_Ya [(size_t)ND * 2048];
__device__ __align__(1024) float g_Yss[(size_t)ND * 1024];
__device__ __align__(1024) float g_Ysa[(size_t)ND * 1024];

// ---------------------------------------------------------------- helpers
__device__ __forceinline__ uint32_t smem_u32(const void* p) {
    uint32_t a;
    asm("{ .reg .u64 t; cvta.to.shared.u64 t, %1; cvt.u32.u64 %0, t; }"
        : "=r"(a) : "l"(p));
    return a;
}
__device__ __forceinline__ float tf32_rna(float x) {
    uint32_t b;
    asm("cvt.rna.tf32.f32 %0, %1;" : "=r"(b) : "f"(x));
    return __uint_as_float(b);
}
__device__ __forceinline__ uint32_t swz(uint32_t off) {
    return off ^ ((off >> 3) & 0x70);  // SW128 (Swizzle<3,4,3>), 128B rows
}
__device__ __forceinline__ void cp16(uint32_t sdst, const float* gsrc) {
    asm volatile("cp.async.cg.shared.global [%0], [%1], 16;"
                 :: "r"(sdst), "l"(__cvta_generic_to_global(gsrc)) : "memory");
}
__device__ __forceinline__ void cp_commit() {
    asm volatile("cp.async.commit_group;" ::: "memory");
}
template <int N>
__device__ __forceinline__ void cp_wait() {
    asm volatile("cp.async.wait_group %0;" :: "n"(N) : "memory");
}
__device__ __forceinline__ void ldsm4(uint32_t* r, uint32_t a) {
    asm volatile("ldmatrix.sync.aligned.m8n8.x4.shared.b16 {%0,%1,%2,%3}, [%4];"
                 : "=r"(r[0]), "=r"(r[1]), "=r"(r[2]), "=r"(r[3]) : "r"(a));
}
__device__ __forceinline__ void mma1688(float* d, const uint32_t* a, const uint32_t* b) {
    asm volatile(
        "mma.sync.aligned.m16n8k8.row.col.f32.tf32.tf32.f32 "
        "{%0,%1,%2,%3}, {%4,%5,%6,%7}, {%8,%9}, {%0,%1,%2,%3};"
        : "+f"(d[0]), "+f"(d[1]), "+f"(d[2]), "+f"(d[3])
        : "r"(a[0]), "r"(a[1]), "r"(a[2]), "r"(a[3]), "r"(b[0]), "r"(b[1]));
}

// ---------------------------------------------------------------- bases
// Co[t][j] = cos(pi*(2j+1)*(2t+1)/8192), t,j < 2048.
__global__ void gen_co_kernel(float4* __restrict__ Co4) {
    int t  = blockIdx.y;
    int q  = blockIdx.x * blockDim.x + threadIdx.x;   // 0..511
    int j0 = q << 2;
    int ko = 2 * t + 1;
    int b  = (2 * j0 + 1) * ko, st = 2 * ko;
    const float s = 1.0f / 8192.0f;
    float4 r;
    r.x = tf32_rna(cospif((float)((b          ) & 16383) * s));
    r.y = tf32_rna(cospif((float)((b +     st) & 16383) * s));
    r.z = tf32_rna(cospif((float)((b + 2 * st) & 16383) * s));
    r.w = tf32_rna(cospif((float)((b + 3 * st) & 16383) * s));
    Co4[(size_t)t * 512 + q] = r;
}

// Cee[w][j] = cos(pi*(2j+1)*w/2048), Ceo[w][j] = cos(pi*(2j+1)*(2w+1)/4096)
__global__ void gen_c2_kernel(float4* __restrict__ Cee4, float4* __restrict__ Ceo4) {
    int w  = blockIdx.y;                              // 0..1023
    int q  = blockIdx.x * blockDim.x + threadIdx.x;   // 0..255
    int j0 = q << 2;
    // Cee: phase mod 4096, scale 1/2048
    int be = (2 * j0 + 1) * w, se = 2 * w;
    const float s1 = 1.0f / 2048.0f;
    float4 re;
    re.x = tf32_rna(cospif((float)((be          ) & 4095) * s1));
    re.y = tf32_rna(cospif((float)((be +     se) & 4095) * s1));
    re.z = tf32_rna(cospif((float)((be + 2 * se) & 4095) * s1));
    re.w = tf32_rna(cospif((float)((be + 3 * se) & 4095) * s1));
    // Ceo: phase mod 8192, scale 1/4096
    int ko = 2 * w + 1;
    int bo = (2 * j0 + 1) * ko, so = 2 * ko;
    const float s2 = 1.0f / 4096.0f;
    float4 ro;
    ro.x = tf32_rna(cospif((float)((bo          ) & 8191) * s2));
    ro.y = tf32_rna(cospif((float)((bo +     so) & 8191) * s2));
    ro.z = tf32_rna(cospif((float)((bo + 2 * so) & 8191) * s2));
    ro.w = tf32_rna(cospif((float)((bo + 3 * so) & 8191) * s2));
    Cee4[(size_t)w * 256 + q] = re;
    Ceo4[(size_t)w * 256 + q] = ro;
}

// Fold rows of length ncin into sum/diff halves, tf32-rounded.
// grid: ((ncin/2/4)/256, 4096), block 256.
__global__ void fold_kernel(const float* __restrict__ src,
                            float* __restrict__ s_out, float* __restrict__ a_out,
                            int ncin) {
    int q   = blockIdx.x * blockDim.x + threadIdx.x;  // float4 idx in output row
    int row = blockIdx.y;
    int ncout = ncin >> 1;
    const float* rp = src + (size_t)row * ncin;
    float4 f  = *(const float4*)&rp[q * 4];
    float4 rv = *(const float4*)&rp[ncin - 4 - q * 4];
    float4 sv, av;
    sv.x = tf32_rna(f.x + rv.w);  av.x = tf32_rna(f.x - rv.w);
    sv.y = tf32_rna(f.y + rv.z);  av.y = tf32_rna(f.y - rv.z);
    sv.z = tf32_rna(f.z + rv.y);  av.z = tf32_rna(f.z - rv.y);
    sv.w = tf32_rna(f.w + rv.x);  av.w = tf32_rna(f.w - rv.x);
    *(float4*)&s_out[(size_t)row * ncout + q * 4] = sv;
    *(float4*)&a_out[(size_t)row * ncout + q * 4] = av;
}

// ---------------------------------------------------------------- GEMM
// Three branches in one launch (long-K CTAs first for wave packing):
//   id <  512: odd      A=Xa  B=Co  K=2048, out rows 2t+1   (stride 2, off 1)
//   id <  768: even-even A=Xss B=Cee K=1024, out rows 4w     (stride 4, off 0)
//   id < 1024: even-odd  A=Xsa B=Ceo K=1024, out rows 4w+2   (stride 4, off 2)
// D[m,n] = sum_k A[m,k]*B[n,k]; transposed store outT[stride*n+off][m].
struct GemmParams {
    const float *A0, *B0, *A1, *B1, *A2, *B2;
    float* outT;
};

__global__ void __launch_bounds__(256, 2) dct_gemm_kernel(GemmParams p) {
    extern __shared__ __align__(1024) char smem[];
    uint32_t sb = smem_u32(smem);
    int tid = threadIdx.x;
    int wid = tid >> 5, lane = tid & 31;

    int id = blockIdx.x;
    const float *A, *B;
    int mb, nbe, K, rstride, roff;
    if (id < 512) {
        A = p.A0; B = p.B0; K = 2048; rstride = 2; roff = 1;
        mb = id >> 4; nbe = id & 15;
    } else if (id < 768) {
        A = p.A1; B = p.B1; K = 1024; rstride = 4; roff = 0;
        int l = id - 512; mb = l >> 3; nbe = l & 7;
    } else {
        A = p.A2; B = p.B2; K = 1024; rstride = 4; roff = 2;
        int l = id - 768; mb = l >> 3; nbe = l & 7;
    }
    int kit = K >> 5;   // K / BK

    // cp.async: 256 threads, 32 rows x 8 chunks per pass; 4 passes per tile.
    int crow = tid >> 3, cch = tid & 7;
    const float* Ag = A + (size_t)(mb * BM + crow) * K + cch * 4;
    const float* Bg = B + (size_t)(nbe * BN + crow) * K + cch * 4;
    uint32_t sA = swz((uint32_t)(crow * 128 + cch * 16));
    size_t r32 = (size_t)32 * K;    // 32 rows of stride K

    auto issue_stage = [&](int k, int s) {
        uint32_t Ab = sb + s * STAGE_BYTES;
        uint32_t Bb = Ab + BM * 128;
        const float* ga = Ag + k * BK;
        const float* gb = Bg + k * BK;
        #pragma unroll
        for (int t = 0; t < 4; t++) {
            uint32_t so = sA + t * 32 * 128;
            cp16(Ab + so, ga + t * r32);
            cp16(Bb + so, gb + t * r32);
        }
    };

    #pragma unroll
    for (int s = 0; s < STAGES - 1; s++) {
        issue_stage(s, s);
        cp_commit();
    }

    // warp grid: 4 (m) x 2 (n); warp tile 32 x 64
    int WM = (wid >> 1) * 32;
    int WN = (wid & 1) * 64;

    float d[2][8][4];
    #pragma unroll
    for (int mt = 0; mt < 2; mt++)
        #pragma unroll
        for (int nt = 0; nt < 8; nt++)
            #pragma unroll
            for (int j = 0; j < 4; j++) d[mt][nt][j] = 0.0f;

    uint32_t aoff = (uint32_t)((lane & 15) * 128 + (lane >> 4) * 16);
    uint32_t boff = (uint32_t)(((lane & 7) + ((lane >> 4) << 3)) * 128
                               + ((lane >> 3) & 1) * 16);

    int s = 0;
    for (int k = 0; k < kit; k++) {
        cp_wait<STAGES - 2>();       // stage-k data arrived (this thread)
        __syncthreads();             // visible to all; stage k-1 fully consumed
        if (k + STAGES - 1 < kit)
            issue_stage(k + STAGES - 1, (k + STAGES - 1) % STAGES);
        cp_commit();                 // empty commits at tail keep count uniform

        uint32_t Ab = sb + s * STAGE_BYTES;
        uint32_t Bb = Ab + BM * 128;

        #pragma unroll
        for (int ks = 0; ks < 4; ks++) {
            uint32_t a0[4], a1[4], bfr[2][4];
            ldsm4(a0, Ab + swz((uint32_t)(WM * 128)        + aoff + ks * 32));
            ldsm4(a1, Ab + swz((uint32_t)((WM + 16) * 128) + aoff + ks * 32));
            // first half: n-cols [WN, WN+32)
            ldsm4(bfr[0], Bb + swz((uint32_t)(WN * 128)        + boff + ks * 32));
            ldsm4(bfr[1], Bb + swz((uint32_t)((WN + 16) * 128) + boff + ks * 32));
            #pragma unroll
            for (int nt = 0; nt < 4; nt++) {
                const uint32_t* bb = &bfr[nt >> 1][(nt & 1) * 2];
                mma1688(d[0][nt], a0, bb);
                mma1688(d[1][nt], a1, bb);
            }
            // second half: n-cols [WN+32, WN+64)
            ldsm4(bfr[0], Bb + swz((uint32_t)((WN + 32) * 128) + boff + ks * 32));
            ldsm4(bfr[1], Bb + swz((uint32_t)((WN + 48) * 128) + boff + ks * 32));
            #pragma unroll
            for (int nt = 0; nt < 4; nt++) {
                const uint32_t* bb = &bfr[nt >> 1][(nt & 1) * 2];
                mma1688(d[0][nt + 4], a0, bb);
                mma1688(d[1][nt + 4], a1, bb);
            }
        }
        s = (s == STAGES - 1) ? 0 : s + 1;
    }

    // -------- epilogue: transpose through SMEM, coalesced float4 stores
    cp_wait<0>();
    __syncthreads();
    float* T = (float*)smem;  // [128][132] = 67.6KB <= 96KB
    int g = lane >> 2, tig = lane & 3;
    #pragma unroll
    for (int mt = 0; mt < 2; mt++) {
        #pragma unroll
        for (int nt = 0; nt < 8; nt++) {
            int m = WM + mt * 16 + g;
            int n = WN + nt * 8 + 2 * tig;
            T[n * 132 + m]           = d[mt][nt][0];
            T[(n + 1) * 132 + m]     = d[mt][nt][1];
            T[n * 132 + m + 8]       = d[mt][nt][2];
            T[(n + 1) * 132 + m + 8] = d[mt][nt][3];
        }
    }
    __syncthreads();
    #pragma unroll
    for (int it = 0; it < 16; it++) {
        int i = tid + it * 256;
        int r = i >> 5, c = (i & 31) * 4;
        float4 v = *(float4*)&T[r * 132 + c];
        size_t orow = (size_t)(rstride * (nbe * BN + r) + roff);
        *(float4*)&p.outT[orow * ND + mb * BM + c] = v;
    }
}

// ---------------------------------------------------------------- host
extern "C" void kernel_launch(void* const* d_in, const int* in_sizes, int n_in,
                              void* d_out, int out_size) {
    void *pCo, *pCee, *pCeo, *pXs, *pXa, *pXss, *pXsa;
    void *pYt, *pYs, *pYa, *pYss, *pYsa;
    cudaGetSymbolAddress(&pCo,  g_Co);
    cudaGetSymbolAddress(&pCee, g_Cee);
    cudaGetSymbolAddress(&pCeo, g_Ceo);
    cudaGetSymbolAddress(&pXs,  g_Xs);
    cudaGetSymbolAddress(&pXa,  g_Xa);
    cudaGetSymbolAddress(&pXss, g_Xss);
    cudaGetSymbolAddress(&pXsa, g_Xsa);
    cudaGetSymbolAddress(&pYt,  g_Yt);
    cudaGetSymbolAddress(&pYs,  g_Ys);
    cudaGetSymbolAddress(&pYa,  g_Ya);
    cudaGetSymbolAddress(&pYss, g_Yss);
    cudaGetSymbolAddress(&pYsa, g_Ysa);

    gen_co_kernel<<<dim3(2, 2048), 256>>>((float4*)pCo);
    gen_c2_kernel<<<dim3(1, 1024), 256>>>((float4*)pCee, (float4*)pCeo);

    // fold input: x(4096) -> Xs,Xa(2048); Xs -> Xss,Xsa(1024)
    fold_kernel<<<dim3(2, ND), 256>>>((const float*)d_in[0],
                                      (float*)pXs, (float*)pXa, ND);
    fold_kernel<<<dim3(1, ND), 256>>>((const float*)pXs,
                                      (float*)pXss, (float*)pXsa, 2048);

    cudaFuncSetAttribute(dct_gemm_kernel,
                         cudaFuncAttributeMaxDynamicSharedMemorySize, SMEM_TOTAL);

    // Pass A -> Yt[v][i]
    GemmParams pa;
    pa.A0 = (const float*)pXa;  pa.B0 = (const float*)pCo;
    pa.A1 = (const float*)pXss; pa.B1 = (const float*)pCee;
    pa.A2 = (const float*)pXsa; pa.B2 = (const float*)pCeo;
    pa.outT = (float*)pYt;
    dct_gemm_kernel<<<1024, 256, SMEM_TOTAL>>>(pa);

    // fold Yt along i: Yt(4096) -> Ys,Ya(2048); Ys -> Yss,Ysa(1024)
    fold_kernel<<<dim3(2, ND), 256>>>((const float*)pYt,
                                      (float*)pYs, (float*)pYa, ND);
    fold_kernel<<<dim3(1, ND), 256>>>((const float*)pYs,
                                      (float*)pYss, (float*)pYsa, 2048);

    // Pass B -> out[u][v]
    GemmParams pb;
    pb.A0 = (const float*)pYa;  pb.B0 = (const float*)pCo;
    pb.A1 = (const float*)pYss; pb.B1 = (const float*)pCee;
    pb.A2 = (const float*)pYsa; pb.B2 = (const float*)pCeo;
    pb.outT = (float*)d_out;
    dct_gemm_kernel<<<1024, 256, SMEM_TOTAL>>>(pb);
}

// round 9
// speedup vs baseline: 1.4801x; 1.1439x over previous
#include <cuda_runtime.h>
#include <cstdint>

#define ND 4096
#define BM 128
#define BN 128
#define BK 32
#define STAGES 3

#define STAGE_BYTES ((BM + BN) * BK * 4)          // 32 KB
#define SMEM_TOTAL (STAGES * STAGE_BYTES)         // 96 KB -> 2 CTAs/SM

// Scratch (device globals are the sanctioned scratch; no cudaMalloc).
__device__ __align__(1024) float g_Co  [(size_t)2048 * 2048]; // cos(pi(2j+1)(2t+1)/8192)
__device__ __align__(1024) float g_Ceo [(size_t)1024 * 1024]; // cos(pi(2j+1)(2w+1)/4096)
__device__ __align__(1024) float g_Ceee[(size_t)512 * 512];   // cos(pi(2j+1)r/1024)
__device__ __align__(1024) float g_Ceeo[(size_t)512 * 512];   // cos(pi(2j+1)(2r+1)/2048)
__device__ __align__(1024) float g_Xa  [(size_t)ND * 2048];
__device__ __align__(1024) float g_Xsa [(size_t)ND * 1024];
__device__ __align__(1024) float g_Xsss[(size_t)ND * 512];
__device__ __align__(1024) float g_Xssa[(size_t)ND * 512];
__device__ __align__(1024) float g_Yt  [(size_t)ND * ND];
__device__ __align__(1024) float g_Ya  [(size_t)ND * 2048];
__device__ __align__(1024) float g_Ysa [(size_t)ND * 1024];
__device__ __align__(1024) float g_Ysss[(size_t)ND * 512];
__device__ __align__(1024) float g_Yssa[(size_t)ND * 512];

// ---------------------------------------------------------------- helpers
__device__ __forceinline__ uint32_t smem_u32(const void* p) {
    uint32_t a;
    asm("{ .reg .u64 t; cvta.to.shared.u64 t, %1; cvt.u32.u64 %0, t; }"
        : "=r"(a) : "l"(p));
    return a;
}
__device__ __forceinline__ float tf32_rna(float x) {
    uint32_t b;
    asm("cvt.rna.tf32.f32 %0, %1;" : "=r"(b) : "f"(x));
    return __uint_as_float(b);
}
__device__ __forceinline__ uint32_t swz(uint32_t off) {
    return off ^ ((off >> 3) & 0x70);  // SW128 (Swizzle<3,4,3>), 128B rows
}
__device__ __forceinline__ void cp16(uint32_t sdst, const float* gsrc) {
    asm volatile("cp.async.cg.shared.global [%0], [%1], 16;"
                 :: "r"(sdst), "l"(__cvta_generic_to_global(gsrc)) : "memory");
}
__device__ __forceinline__ void cp_commit() {
    asm volatile("cp.async.commit_group;" ::: "memory");
}
template <int N>
__device__ __forceinline__ void cp_wait() {
    asm volatile("cp.async.wait_group %0;" :: "n"(N) : "memory");
}
__device__ __forceinline__ void ldsm4(uint32_t* r, uint32_t a) {
    asm volatile("ldmatrix.sync.aligned.m8n8.x4.shared.b16 {%0,%1,%2,%3}, [%4];"
                 : "=r"(r[0]), "=r"(r[1]), "=r"(r[2]), "=r"(r[3]) : "r"(a));
}
__device__ __forceinline__ void mma1688(float* d, const uint32_t* a, const uint32_t* b) {
    asm volatile(
        "mma.sync.aligned.m16n8k8.row.col.f32.tf32.tf32.f32 "
        "{%0,%1,%2,%3}, {%4,%5,%6,%7}, {%8,%9}, {%0,%1,%2,%3};"
        : "+f"(d[0]), "+f"(d[1]), "+f"(d[2]), "+f"(d[3])
        : "r"(a[0]), "r"(a[1]), "r"(a[2]), "r"(a[3]), "r"(b[0]), "r"(b[1]));
}

// ---------------------------------------------------------------- bases
// Co[t][j] = cos(pi*(2j+1)*(2t+1)/8192), t,j < 2048.
__global__ void gen_co_kernel(float4* __restrict__ Co4) {
    int t  = blockIdx.y;
    int q  = blockIdx.x * blockDim.x + threadIdx.x;   // 0..511
    int j0 = q << 2;
    int ko = 2 * t + 1;
    int b  = (2 * j0 + 1) * ko, st = 2 * ko;
    const float s = 1.0f / 8192.0f;
    float4 r;
    r.x = tf32_rna(cospif((float)((b          ) & 16383) * s));
    r.y = tf32_rna(cospif((float)((b +     st) & 16383) * s));
    r.z = tf32_rna(cospif((float)((b + 2 * st) & 16383) * s));
    r.w = tf32_rna(cospif((float)((b + 3 * st) & 16383) * s));
    Co4[(size_t)t * 512 + q] = r;
}

// Ceo[w][j] = cos(pi*(2j+1)*(2w+1)/4096), w,j < 1024.
__global__ void gen_ceo_kernel(float4* __restrict__ Ceo4) {
    int w  = blockIdx.y;
    int q  = threadIdx.x;                             // 0..255
    int j0 = q << 2;
    int ko = 2 * w + 1;
    int b  = (2 * j0 + 1) * ko, st = 2 * ko;
    const float s = 1.0f / 4096.0f;
    float4 r;
    r.x = tf32_rna(cospif((float)((b          ) & 8191) * s));
    r.y = tf32_rna(cospif((float)((b +     st) & 8191) * s));
    r.z = tf32_rna(cospif((float)((b + 2 * st) & 8191) * s));
    r.w = tf32_rna(cospif((float)((b + 3 * st) & 8191) * s));
    Ceo4[(size_t)w * 256 + q] = r;
}

// Ceee[r][j] = cos(pi*(2j+1)*r/1024), Ceeo[r][j] = cos(pi*(2j+1)*(2r+1)/2048)
__global__ void gen_c3_kernel(float4* __restrict__ Ceee4, float4* __restrict__ Ceeo4) {
    int r  = blockIdx.y;                              // 0..511
    int q  = threadIdx.x;                             // 0..127
    int j0 = q << 2;
    // eee: phase mod 2048, scale 1/1024
    int be = (2 * j0 + 1) * r, se = 2 * r;
    const float s1 = 1.0f / 1024.0f;
    float4 re;
    re.x = tf32_rna(cospif((float)((be          ) & 2047) * s1));
    re.y = tf32_rna(cospif((float)((be +     se) & 2047) * s1));
    re.z = tf32_rna(cospif((float)((be + 2 * se) & 2047) * s1));
    re.w = tf32_rna(cospif((float)((be + 3 * se) & 2047) * s1));
    // eeo: phase mod 4096, scale 1/2048
    int ko = 2 * r + 1;
    int bo = (2 * j0 + 1) * ko, so = 2 * ko;
    const float s2 = 1.0f / 2048.0f;
    float4 ro;
    ro.x = tf32_rna(cospif((float)((bo          ) & 4095) * s2));
    ro.y = tf32_rna(cospif((float)((bo +     so) & 4095) * s2));
    ro.z = tf32_rna(cospif((float)((bo + 2 * so) & 4095) * s2));
    ro.w = tf32_rna(cospif((float)((bo + 3 * so) & 4095) * s2));
    Ceee4[(size_t)r * 128 + q] = re;
    Ceeo4[(size_t)r * 128 + q] = ro;
}

// ---------------------------------------------------------------- fold
// One block per row. Three fold levels in SMEM; only GEMM inputs written,
// rounded to tf32 at the leaves (intermediate sums stay full fp32).
//   a1[j] = x[j]-x[4095-j]          (2048, odd branch)
//   s [j] = x[j]+x[4095-j]          (kept in smem)
//   a2[j] = s[j]-s[2047-j]          (1024, even-odd branch)
//   s2[j] = s[j]+s[2047-j]          (kept)
//   s3[j] = s2[j]+s2[1023-j]        (512, even-even-even branch)
//   a3[j] = s2[j]-s2[1023-j]        (512, even-even-odd branch)
__global__ void __launch_bounds__(256) fold3_kernel(
    const float* __restrict__ src,
    float* __restrict__ a1, float* __restrict__ a2,
    float* __restrict__ s3, float* __restrict__ a3)
{
    __shared__ float4 X[1024];    // 4096 floats
    __shared__ float4 S1[512];    // 2048 floats
    __shared__ float4 S2[256];    // 1024 floats
    int tid = threadIdx.x;
    size_t row = blockIdx.x;
    const float4* rp = (const float4*)(src + row * ND);

    #pragma unroll
    for (int i = 0; i < 4; i++) X[tid + i * 256] = rp[tid + i * 256];
    __syncthreads();

    // level 1: 512 output float4s
    #pragma unroll
    for (int i = 0; i < 2; i++) {
        int j = tid + i * 256;
        float4 f = X[j], r = X[1023 - j];
        float4 av, sv;
        av.x = tf32_rna(f.x - r.w);  sv.x = f.x + r.w;
        av.y = tf32_rna(f.y - r.z);  sv.y = f.y + r.z;
        av.z = tf32_rna(f.z - r.y);  sv.z = f.z + r.y;
        av.w = tf32_rna(f.w - r.x);  sv.w = f.w + r.x;
        ((float4*)(a1 + row * 2048))[j] = av;
        S1[j] = sv;
    }
    __syncthreads();

    // level 2: 256 output float4s
    {
        int j = tid;
        float4 f = S1[j], r = S1[511 - j];
        float4 av, sv;
        av.x = tf32_rna(f.x - r.w);  sv.x = f.x + r.w;
        av.y = tf32_rna(f.y - r.z);  sv.y = f.y + r.z;
        av.z = tf32_rna(f.z - r.y);  sv.z = f.z + r.y;
        av.w = tf32_rna(f.w - r.x);  sv.w = f.w + r.x;
        ((float4*)(a2 + row * 1024))[j] = av;
        S2[j] = sv;
    }
    __syncthreads();

    // level 3: 128 output float4s
    if (tid < 128) {
        int j = tid;
        float4 f = S2[j], r = S2[255 - j];
        float4 sv, av;
        sv.x = tf32_rna(f.x + r.w);  av.x = tf32_rna(f.x - r.w);
        sv.y = tf32_rna(f.y + r.z);  av.y = tf32_rna(f.y - r.z);
        sv.z = tf32_rna(f.z + r.y);  av.z = tf32_rna(f.z - r.y);
        sv.w = tf32_rna(f.w + r.x);  av.w = tf32_rna(f.w - r.x);
        ((float4*)(s3 + row * 512))[j] = sv;
        ((float4*)(a3 + row * 512))[j] = av;
    }
}

// ---------------------------------------------------------------- GEMM
// Four branches in one launch (long-K CTAs first for wave packing):
//   id <  512: odd  A=a1 B=Co   K=2048, out rows 2t+1 (stride 2, off 1)
//   id <  768: eo   A=a2 B=Ceo  K=1024, out rows 4w+2 (stride 4, off 2)
//   id <  896: eee  A=s3 B=Ceee K=512,  out rows 8r   (stride 8, off 0)
//   id < 1024: eeo  A=a3 B=Ceeo K=512,  out rows 8r+4 (stride 8, off 4)
// D[m,n] = sum_k A[m,k]*B[n,k]; transposed store outT[stride*n+off][m].
struct GemmParams {
    const float *A0, *B0, *A1, *B1, *A2, *B2, *A3, *B3;
    float* outT;
};

__global__ void __launch_bounds__(256, 2) dct_gemm_kernel(GemmParams p) {
    extern __shared__ __align__(1024) char smem[];
    uint32_t sb = smem_u32(smem);
    int tid = threadIdx.x;
    int wid = tid >> 5, lane = tid & 31;

    int id = blockIdx.x;
    const float *A, *B;
    int mb, nbe, K, rstride, roff;
    if (id < 512) {
        A = p.A0; B = p.B0; K = 2048; rstride = 2; roff = 1;
        mb = id >> 4; nbe = id & 15;
    } else if (id < 768) {
        A = p.A1; B = p.B1; K = 1024; rstride = 4; roff = 2;
        int l = id - 512; mb = l >> 3; nbe = l & 7;
    } else if (id < 896) {
        A = p.A2; B = p.B2; K = 512; rstride = 8; roff = 0;
        int l = id - 768; mb = l >> 2; nbe = l & 3;
    } else {
        A = p.A3; B = p.B3; K = 512; rstride = 8; roff = 4;
        int l = id - 896; mb = l >> 2; nbe = l & 3;
    }
    int kit = K >> 5;   // K / BK

    // cp.async: 256 threads, 32 rows x 8 chunks per pass; 4 passes per tile.
    int crow = tid >> 3, cch = tid & 7;
    const float* Ag = A + (size_t)(mb * BM + crow) * K + cch * 4;
    const float* Bg = B + (size_t)(nbe * BN + crow) * K + cch * 4;
    uint32_t sA = swz((uint32_t)(crow * 128 + cch * 16));
    size_t r32 = (size_t)32 * K;    // 32 rows of stride K

    auto issue_stage = [&](int k, int s) {
        uint32_t Ab = sb + s * STAGE_BYTES;
        uint32_t Bb = Ab + BM * 128;
        const float* ga = Ag + k * BK;
        const float* gb = Bg + k * BK;
        #pragma unroll
        for (int t = 0; t < 4; t++) {
            uint32_t so = sA + t * 32 * 128;
            cp16(Ab + so, ga + t * r32);
            cp16(Bb + so, gb + t * r32);
        }
    };

    #pragma unroll
    for (int s = 0; s < STAGES - 1; s++) {
        issue_stage(s, s);
        cp_commit();
    }

    // warp grid: 4 (m) x 2 (n); warp tile 32 x 64
    int WM = (wid >> 1) * 32;
    int WN = (wid & 1) * 64;

    float d[2][8][4];
    #pragma unroll
    for (int mt = 0; mt < 2; mt++)
        #pragma unroll
        for (int nt = 0; nt < 8; nt++)
            #pragma unroll
            for (int j = 0; j < 4; j++) d[mt][nt][j] = 0.0f;

    uint32_t aoff = (uint32_t)((lane & 15) * 128 + (lane >> 4) * 16);
    uint32_t boff = (uint32_t)(((lane & 7) + ((lane >> 4) << 3)) * 128
                               + ((lane >> 3) & 1) * 16);

    int s = 0;
    for (int k = 0; k < kit; k++) {
        cp_wait<STAGES - 2>();       // stage-k data arrived (this thread)
        __syncthreads();             // visible to all; stage k-1 fully consumed
        if (k + STAGES - 1 < kit)
            issue_stage(k + STAGES - 1, (k + STAGES - 1) % STAGES);
        cp_commit();                 // empty commits at tail keep count uniform

        uint32_t Ab = sb + s * STAGE_BYTES;
        uint32_t Bb = Ab + BM * 128;

        #pragma unroll
        for (int ks = 0; ks < 4; ks++) {
            uint32_t a0[4], a1r[4], bfr[2][4];
            ldsm4(a0,  Ab + swz((uint32_t)(WM * 128)        + aoff + ks * 32));
            ldsm4(a1r, Ab + swz((uint32_t)((WM + 16) * 128) + aoff + ks * 32));
            // first half: n-cols [WN, WN+32)
            ldsm4(bfr[0], Bb + swz((uint32_t)(WN * 128)        + boff + ks * 32));
            ldsm4(bfr[1], Bb + swz((uint32_t)((WN + 16) * 128) + boff + ks * 32));
            #pragma unroll
            for (int nt = 0; nt < 4; nt++) {
                const uint32_t* bb = &bfr[nt >> 1][(nt & 1) * 2];
                mma1688(d[0][nt], a0, bb);
                mma1688(d[1][nt], a1r, bb);
            }
            // second half: n-cols [WN+32, WN+64)
            ldsm4(bfr[0], Bb + swz((uint32_t)((WN + 32) * 128) + boff + ks * 32));
            ldsm4(bfr[1], Bb + swz((uint32_t)((WN + 48) * 128) + boff + ks * 32));
            #pragma unroll
            for (int nt = 0; nt < 4; nt++) {
                const uint32_t* bb = &bfr[nt >> 1][(nt & 1) * 2];
                mma1688(d[0][nt + 4], a0, bb);
                mma1688(d[1][nt + 4], a1r, bb);
            }
        }
        s = (s == STAGES - 1) ? 0 : s + 1;
    }

    // -------- epilogue: transpose through SMEM, coalesced float4 stores
    cp_wait<0>();
    __syncthreads();
    float* T = (float*)smem;  // [128][132] = 67.6KB <= 96KB
    int g = lane >> 2, tig = lane & 3;
    #pragma unroll
    for (int mt = 0; mt < 2; mt++) {
        #pragma unroll
        for (int nt = 0; nt < 8; nt++) {
            int m = WM + mt * 16 + g;
            int n = WN + nt * 8 + 2 * tig;
            T[n * 132 + m]           = d[mt][nt][0];
            T[(n + 1) * 132 + m]     = d[mt][nt][1];
            T[n * 132 + m + 8]       = d[mt][nt][2];
            T[(n + 1) * 132 + m + 8] = d[mt][nt][3];
        }
    }
    __syncthreads();
    #pragma unroll
    for (int it = 0; it < 16; it++) {
        int i = tid + it * 256;
        int r = i >> 5, c = (i & 31) * 4;
        float4 v = *(float4*)&T[r * 132 + c];
        size_t orow = (size_t)(rstride * (nbe * BN + r) + roff);
        *(float4*)&p.outT[orow * ND + mb * BM + c] = v;
    }
}

// ---------------------------------------------------------------- host
extern "C" void kernel_launch(void* const* d_in, const int* in_sizes, int n_in,
                              void* d_out, int out_size) {
    void *pCo, *pCeo, *pCeee, *pCeeo;
    void *pXa, *pXsa, *pXsss, *pXssa;
    void *pYt, *pYa, *pYsa, *pYsss, *pYssa;
    cudaGetSymbolAddress(&pCo,   g_Co);
    cudaGetSymbolAddress(&pCeo,  g_Ceo);
    cudaGetSymbolAddress(&pCeee, g_Ceee);
    cudaGetSymbolAddress(&pCeeo, g_Ceeo);
    cudaGetSymbolAddress(&pXa,   g_Xa);
    cudaGetSymbolAddress(&pXsa,  g_Xsa);
    cudaGetSymbolAddress(&pXsss, g_Xsss);
    cudaGetSymbolAddress(&pXssa, g_Xssa);
    cudaGetSymbolAddress(&pYt,   g_Yt);
    cudaGetSymbolAddress(&pYa,   g_Ya);
    cudaGetSymbolAddress(&pYsa,  g_Ysa);
    cudaGetSymbolAddress(&pYsss, g_Ysss);
    cudaGetSymbolAddress(&pYssa, g_Yssa);

    gen_co_kernel<<<dim3(2, 2048), 256>>>((float4*)pCo);
    gen_ceo_kernel<<<dim3(1, 1024), 256>>>((float4*)pCeo);
    gen_c3_kernel<<<dim3(1, 512), 128>>>((float4*)pCeee, (float4*)pCeeo);

    fold3_kernel<<<ND, 256>>>((const float*)d_in[0],
                              (float*)pXa, (float*)pXsa,
                              (float*)pXsss, (float*)pXssa);

    cudaFuncSetAttribute(dct_gemm_kernel,
                         cudaFuncAttributeMaxDynamicSharedMemorySize, SMEM_TOTAL);

    // Pass A -> Yt[v][i]
    GemmParams pa;
    pa.A0 = (const float*)pXa;   pa.B0 = (const float*)pCo;
    pa.A1 = (const float*)pXsa;  pa.B1 = (const float*)pCeo;
    pa.A2 = (const float*)pXsss; pa.B2 = (const float*)pCeee;
    pa.A3 = (const float*)pXssa; pa.B3 = (const float*)pCeeo;
    pa.outT = (float*)pYt;
    dct_gemm_kernel<<<1024, 256, SMEM_TOTAL>>>(pa);

    fold3_kernel<<<ND, 256>>>((const float*)pYt,
                              (float*)pYa, (float*)pYsa,
                              (float*)pYsss, (float*)pYssa);

    // Pass B -> out[u][v]
    GemmParams pb;
    pb.A0 = (const float*)pYa;   pb.B0 = (const float*)pCo;
    pb.A1 = (const float*)pYsa;  pb.B1 = (const float*)pCeo;
    pb.A2 = (const float*)pYsss; pb.B2 = (const float*)pCeee;
    pb.A3 = (const float*)pYssa; pb.B3 = (const float*)pCeeo;
    pb.outT = (float*)d_out;
    dct_gemm_kernel<<<1024, 256, SMEM_TOTAL>>>(pb);
}

// round 10
// speedup vs baseline: 1.8709x; 1.2641x over previous
#include <cuda_runtime.h>
#include <cstdint>

#define ND 4096
#define BM 128
#define BN 128
#define BK 32
#define STAGES 3

#define STAGE_BYTES ((BM + BN) * BK * 4)          // 32 KB
#define SMEM_TOTAL (STAGES * STAGE_BYTES)         // 96 KB -> 2 CTAs/SM

// Scratch (device globals are the sanctioned scratch; no cudaMalloc).
__device__ __align__(1024) float g_Bc  [(size_t)1024 * 1024]; // cos(pi(2r+1)(2t+1)/4096)
__device__ __align__(1024) float g_Bs  [(size_t)1024 * 1024]; // sin(pi(2r+1)(2t+1)/4096)
__device__ __align__(1024) float g_Ceo [(size_t)1024 * 1024]; // cos(pi(2j+1)(2w+1)/4096)
__device__ __align__(1024) float g_Ceee[(size_t)512 * 512];   // cos(pi(2j+1)r/1024)
__device__ __align__(1024) float g_Ceeo[(size_t)512 * 512];   // cos(pi(2j+1)(2r+1)/2048)
// pass-A fold outputs
__device__ __align__(1024) float g_Ds  [(size_t)ND * 1024];   // s = a1[2r]+a1[2r+1]
__device__ __align__(1024) float g_Dd  [(size_t)ND * 1024];   // d = a1[2r]-a1[2r+1]
__device__ __align__(1024) float g_Xsa [(size_t)ND * 1024];
__device__ __align__(1024) float g_Xsss[(size_t)ND * 512];
__device__ __align__(1024) float g_Xssa[(size_t)ND * 512];
// odd-branch partial results (shared between passes)
__device__ __align__(1024) float g_Sct [(size_t)1024 * ND];
__device__ __align__(1024) float g_Sdt [(size_t)1024 * ND];
// intermediate + pass-B fold outputs
__device__ __align__(1024) float g_Yt  [(size_t)ND * ND];
__device__ __align__(1024) float g_Es  [(size_t)ND * 1024];
__device__ __align__(1024) float g_Ed  [(size_t)ND * 1024];
__device__ __align__(1024) float g_Ysa [(size_t)ND * 1024];
__device__ __align__(1024) float g_Ysss[(size_t)ND * 512];
__device__ __align__(1024) float g_Yssa[(size_t)ND * 512];

// ---------------------------------------------------------------- helpers
__device__ __forceinline__ uint32_t smem_u32(const void* p) {
    uint32_t a;
    asm("{ .reg .u64 t; cvta.to.shared.u64 t, %1; cvt.u32.u64 %0, t; }"
        : "=r"(a) : "l"(p));
    return a;
}
__device__ __forceinline__ float tf32_rna(float x) {
    uint32_t b;
    asm("cvt.rna.tf32.f32 %0, %1;" : "=r"(b) : "f"(x));
    return __uint_as_float(b);
}
__device__ __forceinline__ uint32_t swz(uint32_t off) {
    return off ^ ((off >> 3) & 0x70);  // SW128 (Swizzle<3,4,3>), 128B rows
}
__device__ __forceinline__ void cp16(uint32_t sdst, const float* gsrc) {
    asm volatile("cp.async.cg.shared.global [%0], [%1], 16;"
                 :: "r"(sdst), "l"(__cvta_generic_to_global(gsrc)) : "memory");
}
__device__ __forceinline__ void cp_commit() {
    asm volatile("cp.async.commit_group;" ::: "memory");
}
template <int N>
__device__ __forceinline__ void cp_wait() {
    asm volatile("cp.async.wait_group %0;" :: "n"(N) : "memory");
}
__device__ __forceinline__ void ldsm4(uint32_t* r, uint32_t a) {
    asm volatile("ldmatrix.sync.aligned.m8n8.x4.shared.b16 {%0,%1,%2,%3}, [%4];"
                 : "=r"(r[0]), "=r"(r[1]), "=r"(r[2]), "=r"(r[3]) : "r"(a));
}
__device__ __forceinline__ void mma1688(float* d, const uint32_t* a, const uint32_t* b) {
    asm volatile(
        "mma.sync.aligned.m16n8k8.row.col.f32.tf32.tf32.f32 "
        "{%0,%1,%2,%3}, {%4,%5,%6,%7}, {%8,%9}, {%0,%1,%2,%3};"
        : "+f"(d[0]), "+f"(d[1]), "+f"(d[2]), "+f"(d[3])
        : "r"(a[0]), "r"(a[1]), "r"(a[2]), "r"(a[3]), "r"(b[0]), "r"(b[1]));
}

// ---------------------------------------------------------------- bases
// Bc[t][r] = cos(pi(2r+1)(2t+1)/4096), Bs[t][r] = sin(same), t,r < 1024.
__global__ void gen_bcbs_kernel(float4* __restrict__ Bc4, float4* __restrict__ Bs4) {
    int t  = blockIdx.y;
    int q  = threadIdx.x;                 // 0..255 (float4 over r)
    int r0 = q << 2;
    int kt = 2 * t + 1;
    int b  = (2 * r0 + 1) * kt, st = 2 * kt;
    const float s = 1.0f / 4096.0f;
    float4 rc, rs;
    rc.x = tf32_rna(cospif((float)((b          ) & 8191) * s));
    rc.y = tf32_rna(cospif((float)((b +     st) & 8191) * s));
    rc.z = tf32_rna(cospif((float)((b + 2 * st) & 8191) * s));
    rc.w = tf32_rna(cospif((float)((b + 3 * st) & 8191) * s));
    rs.x = tf32_rna(sinpif((float)((b          ) & 8191) * s));
    rs.y = tf32_rna(sinpif((float)((b +     st) & 8191) * s));
    rs.z = tf32_rna(sinpif((float)((b + 2 * st) & 8191) * s));
    rs.w = tf32_rna(sinpif((float)((b + 3 * st) & 8191) * s));
    Bc4[(size_t)t * 256 + q] = rc;
    Bs4[(size_t)t * 256 + q] = rs;
}

// Ceo[w][j] = cos(pi*(2j+1)*(2w+1)/4096), w,j < 1024.
__global__ void gen_ceo_kernel(float4* __restrict__ Ceo4) {
    int w  = blockIdx.y;
    int q  = threadIdx.x;
    int j0 = q << 2;
    int ko = 2 * w + 1;
    int b  = (2 * j0 + 1) * ko, st = 2 * ko;
    const float s = 1.0f / 4096.0f;
    float4 r;
    r.x = tf32_rna(cospif((float)((b          ) & 8191) * s));
    r.y = tf32_rna(cospif((float)((b +     st) & 8191) * s));
    r.z = tf32_rna(cospif((float)((b + 2 * st) & 8191) * s));
    r.w = tf32_rna(cospif((float)((b + 3 * st) & 8191) * s));
    Ceo4[(size_t)w * 256 + q] = r;
}

// Ceee[r][j] = cos(pi*(2j+1)*r/1024), Ceeo[r][j] = cos(pi*(2j+1)*(2r+1)/2048)
__global__ void gen_c3_kernel(float4* __restrict__ Ceee4, float4* __restrict__ Ceeo4) {
    int r  = blockIdx.y;                  // 0..511
    int q  = threadIdx.x;                 // 0..127
    int j0 = q << 2;
    int be = (2 * j0 + 1) * r, se = 2 * r;
    const float s1 = 1.0f / 1024.0f;
    float4 re;
    re.x = tf32_rna(cospif((float)((be          ) & 2047) * s1));
    re.y = tf32_rna(cospif((float)((be +     se) & 2047) * s1));
    re.z = tf32_rna(cospif((float)((be + 2 * se) & 2047) * s1));
    re.w = tf32_rna(cospif((float)((be + 3 * se) & 2047) * s1));
    int ko = 2 * r + 1;
    int bo = (2 * j0 + 1) * ko, so = 2 * ko;
    const float s2 = 1.0f / 2048.0f;
    float4 ro;
    ro.x = tf32_rna(cospif((float)((bo          ) & 4095) * s2));
    ro.y = tf32_rna(cospif((float)((bo +     so) & 4095) * s2));
    ro.z = tf32_rna(cospif((float)((bo + 2 * so) & 4095) * s2));
    ro.w = tf32_rna(cospif((float)((bo + 3 * so) & 4095) * s2));
    Ceee4[(size_t)r * 128 + q] = re;
    Ceeo4[(size_t)r * 128 + q] = ro;
}

// ---------------------------------------------------------------- fold
// One block per row. All levels in SMEM, leaves tf32-rounded:
//   a1[j] = x[j]-x[4095-j]  (fp32, kept in smem)
//   ds[r] = a1[2r]+a1[2r+1], dd[r] = a1[2r]-a1[2r+1]   (1024, odd DCT-IV split)
//   ss[j] = x[j]+x[4095-j]  (fp32)
//   a2[j] = ss[j]-ss[2047-j] (1024, even-odd);  s2 = ss+rev(ss)
//   s3    = s2+rev(s2) (512); a3 = s2-rev(s2) (512)
__global__ void __launch_bounds__(256) fold3_kernel(
    const float* __restrict__ src,
    float* __restrict__ ds, float* __restrict__ dd,
    float* __restrict__ a2, float* __restrict__ s3, float* __restrict__ a3)
{
    __shared__ float4 X[1024];     // 16 KB
    __shared__ float4 A1[512];     // 8 KB
    __shared__ float4 SS1[512];    // 8 KB
    __shared__ float4 S2[256];     // 4 KB
    int tid = threadIdx.x;
    size_t row = blockIdx.x;
    const float4* rp = (const float4*)(src + row * ND);

    #pragma unroll
    for (int i = 0; i < 4; i++) X[tid + i * 256] = rp[tid + i * 256];
    __syncthreads();

    // level 1 (fp32, unrounded)
    #pragma unroll
    for (int i = 0; i < 2; i++) {
        int j = tid + i * 256;
        float4 f = X[j], r = X[1023 - j];
        float4 av, sv;
        av.x = f.x - r.w;  sv.x = f.x + r.w;
        av.y = f.y - r.z;  sv.y = f.y + r.z;
        av.z = f.z - r.y;  sv.z = f.z + r.y;
        av.w = f.w - r.x;  sv.w = f.w + r.x;
        A1[j] = av;  SS1[j] = sv;
    }
    __syncthreads();

    // odd-branch DCT-IV split: pairs within a1
    {
        int m = tid;   // 0..255
        float4 f0 = A1[2 * m], f1 = A1[2 * m + 1];
        float4 sv, dv;
        sv.x = tf32_rna(f0.x + f0.y);  dv.x = tf32_rna(f0.x - f0.y);
        sv.y = tf32_rna(f0.z + f0.w);  dv.y = tf32_rna(f0.z - f0.w);
        sv.z = tf32_rna(f1.x + f1.y);  dv.z = tf32_rna(f1.x - f1.y);
        sv.w = tf32_rna(f1.z + f1.w);  dv.w = tf32_rna(f1.z - f1.w);
        ((float4*)(ds + row * 1024))[m] = sv;
        ((float4*)(dd + row * 1024))[m] = dv;
    }

    // level 2 on sums
    {
        int j = tid;   // 0..255
        float4 f = SS1[j], r = SS1[511 - j];
        float4 av, sv;
        av.x = tf32_rna(f.x - r.w);  sv.x = f.x + r.w;
        av.y = tf32_rna(f.y - r.z);  sv.y = f.y + r.z;
        av.z = tf32_rna(f.z - r.y);  sv.z = f.z + r.y;
        av.w = tf32_rna(f.w - r.x);  sv.w = f.w + r.x;
        ((float4*)(a2 + row * 1024))[j] = av;
        S2[j] = sv;
    }
    __syncthreads();

    // level 3
    if (tid < 128) {
        int j = tid;
        float4 f = S2[j], r = S2[255 - j];
        float4 sv, av;
        sv.x = tf32_rna(f.x + r.w);  av.x = tf32_rna(f.x - r.w);
        sv.y = tf32_rna(f.y + r.z);  av.y = tf32_rna(f.y - r.z);
        sv.z = tf32_rna(f.z + r.y);  av.z = tf32_rna(f.z - r.y);
        sv.w = tf32_rna(f.w + r.x);  av.w = tf32_rna(f.w - r.x);
        ((float4*)(s3 + row * 512))[j] = sv;
        ((float4*)(a3 + row * 512))[j] = av;
    }
}

// ---------------------------------------------------------------- rotate
// O[2t+1][i] = cosd*Sc[t][i] + sind*Sd[t][i]
// O[4095-2t][i] = -sind*Sc[t][i] + cosd*Sd[t][i],  d = pi(2t+1)/8192.
__global__ void __launch_bounds__(256) rotate_kernel(
    const float4* __restrict__ Sct, const float4* __restrict__ Sdt,
    float* __restrict__ out)
{
    int t = blockIdx.y;
    int q = blockIdx.x * 256 + threadIdx.x;     // 0..1023 float4 per row
    float arg = (float)(2 * t + 1) * (1.0f / 8192.0f);
    float cs = cospif(arg), sn = sinpif(arg);
    float4 a = Sct[(size_t)t * 1024 + q];
    float4 b = Sdt[(size_t)t * 1024 + q];
    float4 o1, o2;
    o1.x = cs * a.x + sn * b.x;  o2.x = cs * b.x - sn * a.x;
    o1.y = cs * a.y + sn * b.y;  o2.y = cs * b.y - sn * a.y;
    o1.z = cs * a.z + sn * b.z;  o2.z = cs * b.z - sn * a.z;
    o1.w = cs * a.w + sn * b.w;  o2.w = cs * b.w - sn * a.w;
    ((float4*)(out + (size_t)(2 * t + 1) * ND))[q]    = o1;
    ((float4*)(out + (size_t)(4095 - 2 * t) * ND))[q] = o2;
}

// ---------------------------------------------------------------- GEMM
// Five branches, one launch (kit=32 first for wave packing):
//   id<256 : Sc  A=ds B=Bc   K=1024 -> Sct rows t    (stride 1, off 0)
//   id<512 : Sd  A=dd B=Bs   K=1024 -> Sdt rows t    (stride 1, off 0)
//   id<768 : eo  A=a2 B=Ceo  K=1024 -> out rows 4w+2 (stride 4, off 2)
//   id<896 : eee A=s3 B=Ceee K=512  -> out rows 8r   (stride 8, off 0)
//   id<1024: eeo A=a3 B=Ceeo K=512  -> out rows 8r+4 (stride 8, off 4)
struct GemmParams {
    const float* A[5];
    const float* B[5];
    float*       O[5];
};

__global__ void __launch_bounds__(256, 2) dct_gemm_kernel(GemmParams p) {
    extern __shared__ __align__(1024) char smem[];
    uint32_t sb = smem_u32(smem);
    int tid = threadIdx.x;
    int wid = tid >> 5, lane = tid & 31;

    int id = blockIdx.x;
    int bi, l, K, rstride, roff, mb, nbe;
    if (id < 256)      { bi = 0; l = id;       K = 1024; rstride = 1; roff = 0; }
    else if (id < 512) { bi = 1; l = id - 256; K = 1024; rstride = 1; roff = 0; }
    else if (id < 768) { bi = 2; l = id - 512; K = 1024; rstride = 4; roff = 2; }
    else if (id < 896) { bi = 3; l = id - 768; K = 512;  rstride = 8; roff = 0; }
    else               { bi = 4; l = id - 896; K = 512;  rstride = 8; roff = 4; }
    if (K == 1024) { mb = l >> 3; nbe = l & 7; }
    else           { mb = l >> 2; nbe = l & 3; }
    const float* A = p.A[bi];
    const float* B = p.B[bi];
    float* outT = p.O[bi];
    int kit = K >> 5;

    // cp.async: 256 threads, 32 rows x 8 chunks per pass; 4 passes per tile.
    int crow = tid >> 3, cch = tid & 7;
    const float* Ag = A + (size_t)(mb * BM + crow) * K + cch * 4;
    const float* Bg = B + (size_t)(nbe * BN + crow) * K + cch * 4;
    uint32_t sA = swz((uint32_t)(crow * 128 + cch * 16));
    size_t r32 = (size_t)32 * K;

    auto issue_stage = [&](int k, int s) {
        uint32_t Ab = sb + s * STAGE_BYTES;
        uint32_t Bb = Ab + BM * 128;
        const float* ga = Ag + k * BK;
        const float* gb = Bg + k * BK;
        #pragma unroll
        for (int t = 0; t < 4; t++) {
            uint32_t so = sA + t * 32 * 128;
            cp16(Ab + so, ga + t * r32);
            cp16(Bb + so, gb + t * r32);
        }
    };

    #pragma unroll
    for (int s = 0; s < STAGES - 1; s++) {
        issue_stage(s, s);
        cp_commit();
    }

    // warp grid: 4 (m) x 2 (n); warp tile 32 x 64
    int WM = (wid >> 1) * 32;
    int WN = (wid & 1) * 64;

    float d[2][8][4];
    #pragma unroll
    for (int mt = 0; mt < 2; mt++)
        #pragma unroll
        for (int nt = 0; nt < 8; nt++)
            #pragma unroll
            for (int j = 0; j < 4; j++) d[mt][nt][j] = 0.0f;

    uint32_t aoff = (uint32_t)((lane & 15) * 128 + (lane >> 4) * 16);
    uint32_t boff = (uint32_t)(((lane & 7) + ((lane >> 4) << 3)) * 128
                               + ((lane >> 3) & 1) * 16);

    int s = 0;
    for (int k = 0; k < kit; k++) {
        cp_wait<STAGES - 2>();
        __syncthreads();
        if (k + STAGES - 1 < kit)
            issue_stage(k + STAGES - 1, (k + STAGES - 1) % STAGES);
        cp_commit();

        uint32_t Ab = sb + s * STAGE_BYTES;
        uint32_t Bb = Ab + BM * 128;

        #pragma unroll
        for (int ks = 0; ks < 4; ks++) {
            uint32_t a0[4], a1r[4], bfr[2][4];
            ldsm4(a0,  Ab + swz((uint32_t)(WM * 128)        + aoff + ks * 32));
            ldsm4(a1r, Ab + swz((uint32_t)((WM + 16) * 128) + aoff + ks * 32));
            ldsm4(bfr[0], Bb + swz((uint32_t)(WN * 128)        + boff + ks * 32));
            ldsm4(bfr[1], Bb + swz((uint32_t)((WN + 16) * 128) + boff + ks * 32));
            #pragma unroll
            for (int nt = 0; nt < 4; nt++) {
                const uint32_t* bb = &bfr[nt >> 1][(nt & 1) * 2];
                mma1688(d[0][nt], a0, bb);
                mma1688(d[1][nt], a1r, bb);
            }
            ldsm4(bfr[0], Bb + swz((uint32_t)((WN + 32) * 128) + boff + ks * 32));
            ldsm4(bfr[1], Bb + swz((uint32_t)((WN + 48) * 128) + boff + ks * 32));
            #pragma unroll
            for (int nt = 0; nt < 4; nt++) {
                const uint32_t* bb = &bfr[nt >> 1][(nt & 1) * 2];
                mma1688(d[0][nt + 4], a0, bb);
                mma1688(d[1][nt + 4], a1r, bb);
            }
        }
        s = (s == STAGES - 1) ? 0 : s + 1;
    }

    // -------- epilogue: transpose through SMEM, coalesced float4 stores
    cp_wait<0>();
    __syncthreads();
    float* T = (float*)smem;  // [128][132]
    int g = lane >> 2, tig = lane & 3;
    #pragma unroll
    for (int mt = 0; mt < 2; mt++) {
        #pragma unroll
        for (int nt = 0; nt < 8; nt++) {
            int m = WM + mt * 16 + g;
            int n = WN + nt * 8 + 2 * tig;
            T[n * 132 + m]           = d[mt][nt][0];
            T[(n + 1) * 132 + m]     = d[mt][nt][1];
            T[n * 132 + m + 8]       = d[mt][nt][2];
            T[(n + 1) * 132 + m + 8] = d[mt][nt][3];
        }
    }
    __syncthreads();
    #pragma unroll
    for (int it = 0; it < 16; it++) {
        int i = tid + it * 256;
        int r = i >> 5, c = (i & 31) * 4;
        float4 v = *(float4*)&T[r * 132 + c];
        size_t orow = (size_t)(rstride * (nbe * BN + r) + roff);
        *(float4*)&outT[orow * ND + mb * BM + c] = v;
    }
}

// ---------------------------------------------------------------- host
extern "C" void kernel_launch(void* const* d_in, const int* in_sizes, int n_in,
                              void* d_out, int out_size) {
    void *pBc, *pBs, *pCeo, *pCeee, *pCeeo;
    void *pDs, *pDd, *pXsa, *pXsss, *pXssa;
    void *pSct, *pSdt, *pYt, *pEs, *pEd, *pYsa, *pYsss, *pYssa;
    cudaGetSymbolAddress(&pBc,   g_Bc);
    cudaGetSymbolAddress(&pBs,   g_Bs);
    cudaGetSymbolAddress(&pCeo,  g_Ceo);
    cudaGetSymbolAddress(&pCeee, g_Ceee);
    cudaGetSymbolAddress(&pCeeo, g_Ceeo);
    cudaGetSymbolAddress(&pDs,   g_Ds);
    cudaGetSymbolAddress(&pDd,   g_Dd);
    cudaGetSymbolAddress(&pXsa,  g_Xsa);
    cudaGetSymbolAddress(&pXsss, g_Xsss);
    cudaGetSymbolAddress(&pXssa, g_Xssa);
    cudaGetSymbolAddress(&pSct,  g_Sct);
    cudaGetSymbolAddress(&pSdt,  g_Sdt);
    cudaGetSymbolAddress(&pYt,   g_Yt);
    cudaGetSymbolAddress(&pEs,   g_Es);
    cudaGetSymbolAddress(&pEd,   g_Ed);
    cudaGetSymbolAddress(&pYsa,  g_Ysa);
    cudaGetSymbolAddress(&pYsss, g_Ysss);
    cudaGetSymbolAddress(&pYssa, g_Yssa);

    gen_bcbs_kernel<<<dim3(1, 1024), 256>>>((float4*)pBc, (float4*)pBs);
    gen_ceo_kernel<<<dim3(1, 1024), 256>>>((float4*)pCeo);
    gen_c3_kernel<<<dim3(1, 512), 128>>>((float4*)pCeee, (float4*)pCeeo);

    cudaFuncSetAttribute(dct_gemm_kernel,
                         cudaFuncAttributeMaxDynamicSharedMemorySize, SMEM_TOTAL);

    // ---- Pass A: x -> Yt[v][i]
    fold3_kernel<<<ND, 256>>>((const float*)d_in[0],
                              (float*)pDs, (float*)pDd,
                              (float*)pXsa, (float*)pXsss, (float*)pXssa);
    GemmParams pa;
    pa.A[0] = (const float*)pDs;   pa.B[0] = (const float*)pBc;   pa.O[0] = (float*)pSct;
    pa.A[1] = (const float*)pDd;   pa.B[1] = (const float*)pBs;   pa.O[1] = (float*)pSdt;
    pa.A[2] = (const float*)pXsa;  pa.B[2] = (const float*)pCeo;  pa.O[2] = (float*)pYt;
    pa.A[3] = (const float*)pXsss; pa.B[3] = (const float*)pCeee; pa.O[3] = (float*)pYt;
    pa.A[4] = (const float*)pXssa; pa.B[4] = (const float*)pCeeo; pa.O[4] = (float*)pYt;
    dct_gemm_kernel<<<1024, 256, SMEM_TOTAL>>>(pa);
    rotate_kernel<<<dim3(4, 1024), 256>>>((const float4*)pSct, (const float4*)pSdt,
                                          (float*)pYt);

    // ---- Pass B: Yt -> out[u][v]
    fold3_kernel<<<ND, 256>>>((const float*)pYt,
                              (float*)pEs, (float*)pEd,
                              (float*)pYsa, (float*)pYsss, (float*)pYssa);
    GemmParams pb;
    pb.A[0] = (const float*)pEs;   pb.B[0] = (const float*)pBc;   pb.O[0] = (float*)pSct;
    pb.A[1] = (const float*)pEd;   pb.B[1] = (const float*)pBs;   pb.O[1] = (float*)pSdt;
    pb.A[2] = (const float*)pYsa;  pb.B[2] = (const float*)pCeo;  pb.O[2] = (float*)d_out;
    pb.A[3] = (const float*)pYsss; pb.B[3] = (const float*)pCeee; pb.O[3] = (float*)d_out;
    pb.A[4] = (const float*)pYssa; pb.B[4] = (const float*)pCeeo; pb.O[4] = (float*)d_out;
    dct_gemm_kernel<<<1024, 256, SMEM_TOTAL>>>(pb);
    rotate_kernel<<<dim3(4, 1024), 256>>>((const float4*)pSct, (const float4*)pSdt,
                                          (float*)d_out);
}

// round 11
// speedup vs baseline: 2.7819x; 1.4869x over previous
#include <cuda_runtime.h>
#include <cstdint>

#define ND 4096
#define BM 128
#define BN 128
#define BK 32
#define KGEMM 512
#define KIT (KGEMM / BK)        // 16
#define STAGES 3

#define STAGE_BYTES ((BM + BN) * BK * 4)          // 32 KB
#define SMEM_TOTAL (STAGES * STAGE_BYTES)         // 96 KB -> 2 CTAs/SM

// Bases (all 1 MB; L2-resident)
__device__ __align__(1024) float g_Bc5 [(size_t)512 * 512]; // cos(pi(2r+1)(2t+1)/2048)
__device__ __align__(1024) float g_Bs5 [(size_t)512 * 512]; // sin(pi(2r+1)(2t+1)/2048)
__device__ __align__(1024) float g_Ceee[(size_t)512 * 512]; // cos(pi(2j+1)r/1024)
// Fold outputs (shared by both passes), each [4096][512]
__device__ __align__(1024) float g_ss2[(size_t)ND * 512];
__device__ __align__(1024) float g_sd2[(size_t)ND * 512];
__device__ __align__(1024) float g_drs[(size_t)ND * 512];
__device__ __align__(1024) float g_drd[(size_t)ND * 512];
__device__ __align__(1024) float g_a2s[(size_t)ND * 512];
__device__ __align__(1024) float g_a2d[(size_t)ND * 512];
__device__ __align__(1024) float g_s3 [(size_t)ND * 512];
__device__ __align__(1024) float g_a3 [(size_t)ND * 512];
// Rotation scratch (shared by both passes), each [512][4096]
__device__ __align__(1024) float g_Scc[(size_t)512 * ND];
__device__ __align__(1024) float g_Scd[(size_t)512 * ND];
__device__ __align__(1024) float g_Sdc[(size_t)512 * ND];
__device__ __align__(1024) float g_Sdd[(size_t)512 * ND];
__device__ __align__(1024) float g_O2c[(size_t)512 * ND];
__device__ __align__(1024) float g_O2d[(size_t)512 * ND];
// Intermediate
__device__ __align__(1024) float g_Yt [(size_t)ND * ND];

// ---------------------------------------------------------------- helpers
__device__ __forceinline__ uint32_t smem_u32(const void* p) {
    uint32_t a;
    asm("{ .reg .u64 t; cvta.to.shared.u64 t, %1; cvt.u32.u64 %0, t; }"
        : "=r"(a) : "l"(p));
    return a;
}
__device__ __forceinline__ float tf32_rna(float x) {
    uint32_t b;
    asm("cvt.rna.tf32.f32 %0, %1;" : "=r"(b) : "f"(x));
    return __uint_as_float(b);
}
__device__ __forceinline__ uint32_t swz(uint32_t off) {
    return off ^ ((off >> 3) & 0x70);  // SW128 (Swizzle<3,4,3>), 128B rows
}
__device__ __forceinline__ void cp16(uint32_t sdst, const float* gsrc) {
    asm volatile("cp.async.cg.shared.global [%0], [%1], 16;"
                 :: "r"(sdst), "l"(__cvta_generic_to_global(gsrc)) : "memory");
}
__device__ __forceinline__ void cp_commit() {
    asm volatile("cp.async.commit_group;" ::: "memory");
}
template <int N>
__device__ __forceinline__ void cp_wait() {
    asm volatile("cp.async.wait_group %0;" :: "n"(N) : "memory");
}
__device__ __forceinline__ void ldsm4(uint32_t* r, uint32_t a) {
    asm volatile("ldmatrix.sync.aligned.m8n8.x4.shared.b16 {%0,%1,%2,%3}, [%4];"
                 : "=r"(r[0]), "=r"(r[1]), "=r"(r[2]), "=r"(r[3]) : "r"(a));
}
__device__ __forceinline__ void mma1688(float* d, const uint32_t* a, const uint32_t* b) {
    asm volatile(
        "mma.sync.aligned.m16n8k8.row.col.f32.tf32.tf32.f32 "
        "{%0,%1,%2,%3}, {%4,%5,%6,%7}, {%8,%9}, {%0,%1,%2,%3};"
        : "+f"(d[0]), "+f"(d[1]), "+f"(d[2]), "+f"(d[3])
        : "r"(a[0]), "r"(a[1]), "r"(a[2]), "r"(a[3]), "r"(b[0]), "r"(b[1]));
}

// ---------------------------------------------------------------- bases
// Bc5[t][r] = cos(pi(2r+1)(2t+1)/2048), Bs5 = sin(same), t,r < 512.
__global__ void gen_b5_kernel(float4* __restrict__ Bc4, float4* __restrict__ Bs4) {
    int t  = blockIdx.y;
    int q  = threadIdx.x;                 // 0..127
    int r0 = q << 2;
    int kt = 2 * t + 1;
    int b  = (2 * r0 + 1) * kt, st = 2 * kt;
    const float s = 1.0f / 2048.0f;
    float4 rc, rs;
    rc.x = tf32_rna(cospif((float)((b          ) & 4095) * s));
    rc.y = tf32_rna(cospif((float)((b +     st) & 4095) * s));
    rc.z = tf32_rna(cospif((float)((b + 2 * st) & 4095) * s));
    rc.w = tf32_rna(cospif((float)((b + 3 * st) & 4095) * s));
    rs.x = tf32_rna(sinpif((float)((b          ) & 4095) * s));
    rs.y = tf32_rna(sinpif((float)((b +     st) & 4095) * s));
    rs.z = tf32_rna(sinpif((float)((b + 2 * st) & 4095) * s));
    rs.w = tf32_rna(sinpif((float)((b + 3 * st) & 4095) * s));
    Bc4[(size_t)t * 128 + q] = rc;
    Bs4[(size_t)t * 128 + q] = rs;
}

// Ceee[r][j] = cos(pi*(2j+1)*r/1024), r,j < 512.
__global__ void gen_ceee_kernel(float4* __restrict__ C4) {
    int r  = blockIdx.y;
    int q  = threadIdx.x;                 // 0..127
    int j0 = q << 2;
    int b  = (2 * j0 + 1) * r, st = 2 * r;
    const float s = 1.0f / 1024.0f;
    float4 re;
    re.x = tf32_rna(cospif((float)((b          ) & 2047) * s));
    re.y = tf32_rna(cospif((float)((b +     st) & 2047) * s));
    re.z = tf32_rna(cospif((float)((b + 2 * st) & 2047) * s));
    re.w = tf32_rna(cospif((float)((b + 3 * st) & 2047) * s));
    C4[(size_t)r * 128 + q] = re;
}

// ---------------------------------------------------------------- fold
// One block per row; full fold cascade in SMEM, tf32-round at the leaves.
//   a1 = x - rev(x) (2048); ss = x + rev(x)
//   s  = a1[2r]+a1[2r+1];  d = a1[2r]-a1[2r+1]          (1024)
//   ss2= s[2r]+s[2r+1];    sd2= s[2r]-s[2r+1]           (512)
//   dr = rev(d): drs= dr[2r]+dr[2r+1]; drd= dr[2r]-dr[2r+1]
//   a2 = ss - rev(ss) (1024); s2 = ss + rev(ss)
//   a2s= a2[2r]+a2[2r+1];  a2d= a2[2r]-a2[2r+1]         (512)
//   s3 = s2 + rev(s2);     a3 = s2 - rev(s2)            (512)
__global__ void __launch_bounds__(256) fold_kernel(
    const float* __restrict__ src,
    float* __restrict__ ss2, float* __restrict__ sd2,
    float* __restrict__ drs, float* __restrict__ drd,
    float* __restrict__ a2s, float* __restrict__ a2d,
    float* __restrict__ s3,  float* __restrict__ a3)
{
    __shared__ float X[4096];
    __shared__ float A1[2048];
    __shared__ float SS[2048];
    __shared__ float S[1024], D[1024], A2[1024], S2[1024];
    int tid = threadIdx.x;
    size_t row = blockIdx.x;
    const float4* rp = (const float4*)(src + row * ND);

    #pragma unroll
    for (int i = 0; i < 4; i++)
        ((float4*)X)[tid + i * 256] = rp[tid + i * 256];
    __syncthreads();

    #pragma unroll
    for (int i = 0; i < 8; i++) {
        int j = tid + i * 256;
        float a = X[j], b = X[4095 - j];
        A1[j] = a - b;
        SS[j] = a + b;
    }
    __syncthreads();

    #pragma unroll
    for (int i = 0; i < 4; i++) {
        int r = tid + i * 256;
        float p = A1[2 * r], q = A1[2 * r + 1];
        S[r] = p + q;  D[r] = p - q;
        float u = SS[r], v = SS[2047 - r];
        A2[r] = u - v;  S2[r] = u + v;
    }
    __syncthreads();

    #pragma unroll
    for (int i = 0; i < 2; i++) {
        int r = tid + i * 256;
        float p, q;
        p = S[2 * r];        q = S[2 * r + 1];
        ss2[row * 512 + r] = tf32_rna(p + q);
        sd2[row * 512 + r] = tf32_rna(p - q);
        p = D[1023 - 2 * r]; q = D[1022 - 2 * r];   // dr[2r], dr[2r+1]
        drs[row * 512 + r] = tf32_rna(p + q);
        drd[row * 512 + r] = tf32_rna(p - q);
        p = A2[2 * r];       q = A2[2 * r + 1];
        a2s[row * 512 + r] = tf32_rna(p + q);
        a2d[row * 512 + r] = tf32_rna(p - q);
        p = S2[r];           q = S2[1023 - r];
        s3[row * 512 + r]  = tf32_rna(p + q);
        a3[row * 512 + r]  = tf32_rna(p - q);
    }
}

// ---------------------------------------------------------------- rotate
// Fused 2-level rotation. For t < 512 (m = 1023-t):
//   d2 = pi(2t+1)/4096:  Sc_t=c2*Scc+s2*Scd; Sc_m=-s2*Scc+c2*Scd
//                        Dr_t=c2*Sdc+s2*Sdd; Dr_m=-s2*Sdc+c2*Sdd
//   Sd_t=(-1)^t*Dr_t; Sd_m=-(-1)^t*Dr_m
//   d1t= pi(2t+1)/8192: out[2t+1]=c1t*Sc_t+s1t*Sd_t; out[4095-2t]=-s1t*Sc_t+c1t*Sd_t
//   d1m= pi(2047-2t)/8192: out[2047-2t]=c1m*Sc_m+s1m*Sd_m; out[2049+2t]=-s1m*Sc_m+c1m*Sd_m
//   eo: out[4t+2]=c2*O2c+s2*O2d; out[4094-4t]=-s2*O2c+c2*O2d
__global__ void __launch_bounds__(256) rotate_kernel(
    const float4* __restrict__ Scc, const float4* __restrict__ Scd,
    const float4* __restrict__ Sdc, const float4* __restrict__ Sdd,
    const float4* __restrict__ O2c, const float4* __restrict__ O2d,
    float* __restrict__ out)
{
    int t = blockIdx.y;
    int q = blockIdx.x * 256 + threadIdx.x;     // 0..1023 float4 per row
    float c2  = cospif((float)(2 * t + 1) * (1.0f / 4096.0f));
    float s2  = sinpif((float)(2 * t + 1) * (1.0f / 4096.0f));
    float c1t = cospif((float)(2 * t + 1) * (1.0f / 8192.0f));
    float s1t = sinpif((float)(2 * t + 1) * (1.0f / 8192.0f));
    float c1m = cospif((float)(2047 - 2 * t) * (1.0f / 8192.0f));
    float s1m = sinpif((float)(2047 - 2 * t) * (1.0f / 8192.0f));
    float sgn = (t & 1) ? -1.0f : 1.0f;
    size_t off = (size_t)t * 1024 + q;
    float4 scc = Scc[off], scd = Scd[off];
    float4 sdc = Sdc[off], sdd = Sdd[off];
    float4 o2c = O2c[off], o2d = O2d[off];
    float4 o_a, o_b, o_c, o_d, o_e, o_f;
    #pragma unroll
    for (int e = 0; e < 4; e++) {
        float vcc = (&scc.x)[e], vcd = (&scd.x)[e];
        float vdc = (&sdc.x)[e], vdd = (&sdd.x)[e];
        float v2c = (&o2c.x)[e], v2d = (&o2d.x)[e];
        float Sct =  c2 * vcc + s2 * vcd;
        float Scm = -s2 * vcc + c2 * vcd;
        float Drt =  c2 * vdc + s2 * vdd;
        float Drm = -s2 * vdc + c2 * vdd;
        float Sdt =  sgn * Drt;
        float Sdm = -sgn * Drm;
        (&o_a.x)[e] =  c1t * Sct + s1t * Sdt;   // row 2t+1
        (&o_b.x)[e] = -s1t * Sct + c1t * Sdt;   // row 4095-2t
        (&o_c.x)[e] =  c1m * Scm + s1m * Sdm;   // row 2047-2t
        (&o_d.x)[e] = -s1m * Scm + c1m * Sdm;   // row 2049+2t
        (&o_e.x)[e] =  c2 * v2c + s2 * v2d;     // row 4t+2
        (&o_f.x)[e] = -s2 * v2c + c2 * v2d;     // row 4094-4t
    }
    ((float4*)(out + (size_t)(2 * t + 1) * ND))[q]    = o_a;
    ((float4*)(out + (size_t)(4095 - 2 * t) * ND))[q] = o_b;
    ((float4*)(out + (size_t)(2047 - 2 * t) * ND))[q] = o_c;
    ((float4*)(out + (size_t)(2049 + 2 * t) * ND))[q] = o_d;
    ((float4*)(out + (size_t)(4 * t + 2) * ND))[q]    = o_e;
    ((float4*)(out + (size_t)(4094 - 4 * t) * ND))[q] = o_f;
}

// ---------------------------------------------------------------- GEMM
// 8 uniform branches (M=4096, N=512, K=512), 128 CTAs each:
//   bi 0: ss2*Bc5 ->Scc   1: sd2*Bs5 ->Scd   2: drs*Bc5 ->Sdc
//   bi 3: drd*Bs5 ->Sdd   4: a2s*Bc5 ->O2c   5: a2d*Bs5 ->O2d
//   bi 6: s3 *Ceee->out rows 8r    7: a3*Bc5(=Ceeo)->out rows 8r+4
struct GemmParams {
    const float* A[8];
    const float* B[8];
    float*       O[8];
};

__global__ void __launch_bounds__(256, 2) dct_gemm_kernel(GemmParams p) {
    extern __shared__ __align__(1024) char smem[];
    uint32_t sb = smem_u32(smem);
    int tid = threadIdx.x;
    int wid = tid >> 5, lane = tid & 31;

    int id = blockIdx.x;
    int bi = id >> 7;
    int l  = id & 127;
    int mb = l >> 2, nbe = l & 3;
    int rstride = (bi >= 6) ? 8 : 1;
    int roff    = (bi == 7) ? 4 : 0;
    const float* A = p.A[bi];
    const float* B = p.B[bi];
    float* outT = p.O[bi];

    // cp.async: 256 threads, 32 rows x 8 chunks per pass; 4 passes per tile.
    int crow = tid >> 3, cch = tid & 7;
    const float* Ag = A + (size_t)(mb * BM + crow) * KGEMM + cch * 4;
    const float* Bg = B + (size_t)(nbe * BN + crow) * KGEMM + cch * 4;
    uint32_t sA = swz((uint32_t)(crow * 128 + cch * 16));
    const size_t r32 = (size_t)32 * KGEMM;

    auto issue_stage = [&](int k, int s) {
        uint32_t Ab = sb + s * STAGE_BYTES;
        uint32_t Bb = Ab + BM * 128;
        const float* ga = Ag + k * BK;
        const float* gb = Bg + k * BK;
        #pragma unroll
        for (int t = 0; t < 4; t++) {
            uint32_t so = sA + t * 32 * 128;
            cp16(Ab + so, ga + t * r32);
            cp16(Bb + so, gb + t * r32);
        }
    };

    #pragma unroll
    for (int s = 0; s < STAGES - 1; s++) {
        issue_stage(s, s);
        cp_commit();
    }

    // warp grid: 4 (m) x 2 (n); warp tile 32 x 64
    int WM = (wid >> 1) * 32;
    int WN = (wid & 1) * 64;

    float d[2][8][4];
    #pragma unroll
    for (int mt = 0; mt < 2; mt++)
        #pragma unroll
        for (int nt = 0; nt < 8; nt++)
            #pragma unroll
            for (int j = 0; j < 4; j++) d[mt][nt][j] = 0.0f;

    uint32_t aoff = (uint32_t)((lane & 15) * 128 + (lane >> 4) * 16);
    uint32_t boff = (uint32_t)(((lane & 7) + ((lane >> 4) << 3)) * 128
                               + ((lane >> 3) & 1) * 16);

    int s = 0;
    for (int k = 0; k < KIT; k++) {
        cp_wait<STAGES - 2>();
        __syncthreads();
        if (k + STAGES - 1 < KIT)
            issue_stage(k + STAGES - 1, (k + STAGES - 1) % STAGES);
        cp_commit();

        uint32_t Ab = sb + s * STAGE_BYTES;
        uint32_t Bb = Ab + BM * 128;

        #pragma unroll
        for (int ks = 0; ks < 4; ks++) {
            uint32_t a0[4], a1r[4], bfr[2][4];
            ldsm4(a0,  Ab + swz((uint32_t)(WM * 128)        + aoff + ks * 32));
            ldsm4(a1r, Ab + swz((uint32_t)((WM + 16) * 128) + aoff + ks * 32));
            ldsm4(bfr[0], Bb + swz((uint32_t)(WN * 128)        + boff + ks * 32));
            ldsm4(bfr[1], Bb + swz((uint32_t)((WN + 16) * 128) + boff + ks * 32));
            #pragma unroll
            for (int nt = 0; nt < 4; nt++) {
                const uint32_t* bb = &bfr[nt >> 1][(nt & 1) * 2];
                mma1688(d[0][nt], a0, bb);
                mma1688(d[1][nt], a1r, bb);
            }
            ldsm4(bfr[0], Bb + swz((uint32_t)((WN + 32) * 128) + boff + ks * 32));
            ldsm4(bfr[1], Bb + swz((uint32_t)((WN + 48) * 128) + boff + ks * 32));
            #pragma unroll
            for (int nt = 0; nt < 4; nt++) {
                const uint32_t* bb = &bfr[nt >> 1][(nt & 1) * 2];
                mma1688(d[0][nt + 4], a0, bb);
                mma1688(d[1][nt + 4], a1r, bb);
            }
        }
        s = (s == STAGES - 1) ? 0 : s + 1;
    }

    // -------- epilogue: transpose through SMEM, coalesced float4 stores
    cp_wait<0>();
    __syncthreads();
    float* T = (float*)smem;  // [128][132]
    int g = lane >> 2, tig = lane & 3;
    #pragma unroll
    for (int mt = 0; mt < 2; mt++) {
        #pragma unroll
        for (int nt = 0; nt < 8; nt++) {
            int m = WM + mt * 16 + g;
            int n = WN + nt * 8 + 2 * tig;
            T[n * 132 + m]           = d[mt][nt][0];
            T[(n + 1) * 132 + m]     = d[mt][nt][1];
            T[n * 132 + m + 8]       = d[mt][nt][2];
            T[(n + 1) * 132 + m + 8] = d[mt][nt][3];
        }
    }
    __syncthreads();
    #pragma unroll
    for (int it = 0; it < 16; it++) {
        int i = tid + it * 256;
        int r = i >> 5, c = (i & 31) * 4;
        float4 v = *(float4*)&T[r * 132 + c];
        size_t orow = (size_t)(rstride * (nbe * BN + r) + roff);
        *(float4*)&outT[orow * ND + mb * BM + c] = v;
    }
}

// ---------------------------------------------------------------- host
extern "C" void kernel_launch(void* const* d_in, const int* in_sizes, int n_in,
                              void* d_out, int out_size) {
    void *pBc5, *pBs5, *pCeee;
    void *pF[8];
    void *pScc, *pScd, *pSdc, *pSdd, *pO2c, *pO2d, *pYt;
    cudaGetSymbolAddress(&pBc5,  g_Bc5);
    cudaGetSymbolAddress(&pBs5,  g_Bs5);
    cudaGetSymbolAddress(&pCeee, g_Ceee);
    cudaGetSymbolAddress(&pF[0], g_ss2);
    cudaGetSymbolAddress(&pF[1], g_sd2);
    cudaGetSymbolAddress(&pF[2], g_drs);
    cudaGetSymbolAddress(&pF[3], g_drd);
    cudaGetSymbolAddress(&pF[4], g_a2s);
    cudaGetSymbolAddress(&pF[5], g_a2d);
    cudaGetSymbolAddress(&pF[6], g_s3);
    cudaGetSymbolAddress(&pF[7], g_a3);
    cudaGetSymbolAddress(&pScc,  g_Scc);
    cudaGetSymbolAddress(&pScd,  g_Scd);
    cudaGetSymbolAddress(&pSdc,  g_Sdc);
    cudaGetSymbolAddress(&pSdd,  g_Sdd);
    cudaGetSymbolAddress(&pO2c,  g_O2c);
    cudaGetSymbolAddress(&pO2d,  g_O2d);
    cudaGetSymbolAddress(&pYt,   g_Yt);

    gen_b5_kernel<<<dim3(1, 512), 128>>>((float4*)pBc5, (float4*)pBs5);
    gen_ceee_kernel<<<dim3(1, 512), 128>>>((float4*)pCeee);

    cudaFuncSetAttribute(dct_gemm_kernel,
                         cudaFuncAttributeMaxDynamicSharedMemorySize, SMEM_TOTAL);

    GemmParams gp;
    gp.B[0] = (const float*)pBc5;  gp.O[0] = (float*)pScc;
    gp.B[1] = (const float*)pBs5;  gp.O[1] = (float*)pScd;
    gp.B[2] = (const float*)pBc5;  gp.O[2] = (float*)pSdc;
    gp.B[3] = (const float*)pBs5;  gp.O[3] = (float*)pSdd;
    gp.B[4] = (const float*)pBc5;  gp.O[4] = (float*)pO2c;
    gp.B[5] = (const float*)pBs5;  gp.O[5] = (float*)pO2d;
    gp.B[6] = (const float*)pCeee;
    gp.B[7] = (const float*)pBc5;                      // Ceeo == Bc5 (symmetric)
    for (int i = 0; i < 8; i++) gp.A[i] = (const float*)pF[i];

    // ---- Pass A: x -> Yt[v][i]
    fold_kernel<<<ND, 256>>>((const float*)d_in[0],
                             (float*)pF[0], (float*)pF[1], (float*)pF[2], (float*)pF[3],
                             (float*)pF[4], (float*)pF[5], (float*)pF[6], (float*)pF[7]);
    gp.O[6] = (float*)pYt;  gp.O[7] = (float*)pYt;
    dct_gemm_kernel<<<1024, 256, SMEM_TOTAL>>>(gp);
    rotate_kernel<<<dim3(4, 512), 256>>>(
        (const float4*)pScc, (const float4*)pScd, (const float4*)pSdc,
        (const float4*)pSdd, (const float4*)pO2c, (const float4*)pO2d, (float*)pYt);

    // ---- Pass B: Yt -> out[u][v]
    fold_kernel<<<ND, 256>>>((const float*)pYt,
                             (float*)pF[0], (float*)pF[1], (float*)pF[2], (float*)pF[3],
                             (float*)pF[4], (float*)pF[5], (float*)pF[6], (float*)pF[7]);
    gp.O[6] = (float*)d_out;  gp.O[7] = (float*)d_out;
    dct_gemm_kernel<<<1024, 256, SMEM_TOTAL>>>(gp);
    rotate_kernel<<<dim3(4, 512), 256>>>(
        (const float4*)pScc, (const float4*)pScd, (const float4*)pSdc,
        (const float4*)pSdd, (const float4*)pO2c, (const float4*)pO2d, (float*)d_out);
}

// round 12
// speedup vs baseline: 3.1959x; 1.1488x over previous
#include <cuda_runtime.h>
#include <cstdint>

#define ND 4096
#define BM 128
#define BN 128
#define BK 32
#define KGEMM 256
#define KIT (KGEMM / BK)        // 8
#define STAGES 3

#define STAGE_BYTES ((BM + BN) * BK * 4)          // 32 KB
#define SMEM_TOTAL (STAGES * STAGE_BYTES)         // 96 KB -> 2 CTAs/SM

// Bases (tiny; L2/L1-resident)
__device__ __align__(1024) float g_Bc6 [(size_t)256 * 256]; // cos(pi(2r+1)(2t+1)/1024)
__device__ __align__(1024) float g_Bs6 [(size_t)256 * 256]; // sin(pi(2r+1)(2t+1)/1024)
__device__ __align__(1024) float g_Cee7[(size_t)256 * 256]; // cos(pi(2r+1)k/512)
// 16 leaf A-buffers [4096][256] (shared by both passes)
__device__ __align__(1024) float g_L[16][(size_t)ND * 256];
// 14 leaf GEMM outputs [256][4096]
__device__ __align__(1024) float g_P[14][(size_t)256 * ND];
// Intermediate
__device__ __align__(1024) float g_Yt [(size_t)ND * ND];

// ---------------------------------------------------------------- helpers
__device__ __forceinline__ uint32_t smem_u32(const void* p) {
    uint32_t a;
    asm("{ .reg .u64 t; cvta.to.shared.u64 t, %1; cvt.u32.u64 %0, t; }"
        : "=r"(a) : "l"(p));
    return a;
}
__device__ __forceinline__ float tf32_rna(float x) {
    uint32_t b;
    asm("cvt.rna.tf32.f32 %0, %1;" : "=r"(b) : "f"(x));
    return __uint_as_float(b);
}
__device__ __forceinline__ uint32_t swz(uint32_t off) {
    return off ^ ((off >> 3) & 0x70);  // SW128 (Swizzle<3,4,3>), 128B rows
}
__device__ __forceinline__ void cp16(uint32_t sdst, const float* gsrc) {
    asm volatile("cp.async.cg.shared.global [%0], [%1], 16;"
                 :: "r"(sdst), "l"(__cvta_generic_to_global(gsrc)) : "memory");
}
__device__ __forceinline__ void cp_commit() {
    asm volatile("cp.async.commit_group;" ::: "memory");
}
template <int N>
__device__ __forceinline__ void cp_wait() {
    asm volatile("cp.async.wait_group %0;" :: "n"(N) : "memory");
}
__device__ __forceinline__ void ldsm4(uint32_t* r, uint32_t a) {
    asm volatile("ldmatrix.sync.aligned.m8n8.x4.shared.b16 {%0,%1,%2,%3}, [%4];"
                 : "=r"(r[0]), "=r"(r[1]), "=r"(r[2]), "=r"(r[3]) : "r"(a));
}
__device__ __forceinline__ void mma1688(float* d, const uint32_t* a, const uint32_t* b) {
    asm volatile(
        "mma.sync.aligned.m16n8k8.row.col.f32.tf32.tf32.f32 "
        "{%0,%1,%2,%3}, {%4,%5,%6,%7}, {%8,%9}, {%0,%1,%2,%3};"
        : "+f"(d[0]), "+f"(d[1]), "+f"(d[2]), "+f"(d[3])
        : "r"(a[0]), "r"(a[1]), "r"(a[2]), "r"(a[3]), "r"(b[0]), "r"(b[1]));
}

// ---------------------------------------------------------------- bases
// Bc6[t][r] = cos(pi(2r+1)(2t+1)/1024), Bs6 = sin(same), t,r < 256.
__global__ void gen_b6_kernel(float4* __restrict__ Bc4, float4* __restrict__ Bs4) {
    int t  = blockIdx.y;
    int q  = threadIdx.x;                 // 0..63
    int r0 = q << 2;
    int kt = 2 * t + 1;
    int b  = (2 * r0 + 1) * kt, st = 2 * kt;
    const float s = 1.0f / 1024.0f;
    float4 rc, rs;
    rc.x = tf32_rna(cospif((float)((b          ) & 2047) * s));
    rc.y = tf32_rna(cospif((float)((b +     st) & 2047) * s));
    rc.z = tf32_rna(cospif((float)((b + 2 * st) & 2047) * s));
    rc.w = tf32_rna(cospif((float)((b + 3 * st) & 2047) * s));
    rs.x = tf32_rna(sinpif((float)((b          ) & 2047) * s));
    rs.y = tf32_rna(sinpif((float)((b +     st) & 2047) * s));
    rs.z = tf32_rna(sinpif((float)((b + 2 * st) & 2047) * s));
    rs.w = tf32_rna(sinpif((float)((b + 3 * st) & 2047) * s));
    Bc4[(size_t)t * 64 + q] = rc;
    Bs4[(size_t)t * 64 + q] = rs;
}

// Cee7[k][r] = cos(pi*(2r+1)*k/512), k,r < 256.
__global__ void gen_cee7_kernel(float4* __restrict__ C4) {
    int k  = blockIdx.y;
    int q  = threadIdx.x;                 // 0..63
    int r0 = q << 2;
    int b  = (2 * r0 + 1) * k, st = 2 * k;
    const float s = 1.0f / 512.0f;
    float4 re;
    re.x = tf32_rna(cospif((float)((b          ) & 1023) * s));
    re.y = tf32_rna(cospif((float)((b +     st) & 1023) * s));
    re.z = tf32_rna(cospif((float)((b + 2 * st) & 1023) * s));
    re.w = tf32_rna(cospif((float)((b + 3 * st) & 1023) * s));
    C4[(size_t)k * 64 + q] = re;
}

// ---------------------------------------------------------------- fold
// One block per row; full 4-level fold cascade in SMEM, tf32-round at leaves.
// Intermediates (fp32): a1 = x - rev(x), ss = x + rev(x) (2048)
//   S = a1 pair-sum, D = a1 pair-diff (1024)
//   A2 = ss - rev(ss), S2 = ss + rev(ss) (1024)
// 16 leaves (256 each), see index algebra in comments below.
struct FoldOut { float* L[16]; };

__global__ void __launch_bounds__(256) fold_kernel(
    const float* __restrict__ src, FoldOut fo)
{
    __shared__ float X[4096];
    __shared__ float A1[2048];
    __shared__ float SS[2048];
    __shared__ float S[1024], D[1024], A2[1024], S2[1024];
    int tid = threadIdx.x;
    size_t row = blockIdx.x;
    const float4* rp = (const float4*)(src + row * ND);

    #pragma unroll
    for (int i = 0; i < 4; i++)
        ((float4*)X)[tid + i * 256] = rp[tid + i * 256];
    __syncthreads();

    #pragma unroll
    for (int i = 0; i < 8; i++) {
        int j = tid + i * 256;
        float a = X[j], b = X[4095 - j];
        A1[j] = a - b;
        SS[j] = a + b;
    }
    __syncthreads();

    #pragma unroll
    for (int i = 0; i < 4; i++) {
        int r = tid + i * 256;
        float p = A1[2 * r], q = A1[2 * r + 1];
        S[r] = p + q;  D[r] = p - q;
        float u = SS[r], v = SS[2047 - r];
        A2[r] = u - v;  S2[r] = u + v;
    }
    __syncthreads();

    {
        int r = tid;           // 0..255
        // branch 0: ss2 = S pair-sum; leaves from S[4r..4r+3]
        float s0 = S[4*r], s1 = S[4*r+1], s2 = S[4*r+2], s3 = S[4*r+3];
        fo.L[0][row * 256 + r] = tf32_rna((s0 + s1) + (s2 + s3));
        fo.L[1][row * 256 + r] = tf32_rna((s0 + s1) - (s2 + s3));
        // branch 1: u1 = rev(sd2), sd2[j] = S[2j]-S[2j+1]
        // u1s[r] = (S[1022-4r]-S[1023-4r]) + (S[1020-4r]-S[1021-4r])
        float t0 = S[1020-4*r], t1 = S[1021-4*r], t2 = S[1022-4*r], t3 = S[1023-4*r];
        fo.L[2][row * 256 + r] = tf32_rna((t2 - t3) + (t0 - t1));
        fo.L[3][row * 256 + r] = tf32_rna((t2 - t3) - (t0 - t1));
        // branch 2: drs[j] = D[1023-2j]+D[1022-2j]; us2[r] = drs[2r]+drs[2r+1]
        float u0 = D[1020-4*r], u1 = D[1021-4*r], u2 = D[1022-4*r], u3 = D[1023-4*r];
        fo.L[4][row * 256 + r] = tf32_rna((u3 + u2) + (u1 + u0));
        fo.L[5][row * 256 + r] = tf32_rna((u3 + u2) - (u1 + u0));
        // branch 3: u3 = rev(drd), drd[j] = D[1023-2j]-D[1022-2j]
        // u3s[r] = (D[4r+1]-D[4r]) + (D[4r+3]-D[4r+2])
        float d0 = D[4*r], d1 = D[4*r+1], d2 = D[4*r+2], d3 = D[4*r+3];
        fo.L[6][row * 256 + r] = tf32_rna((d1 - d0) + (d3 - d2));
        fo.L[7][row * 256 + r] = tf32_rna((d1 - d0) - (d3 - d2));
        // branch 4: a2s = A2 pair-sum
        float a0 = A2[4*r], a1 = A2[4*r+1], a2 = A2[4*r+2], a3 = A2[4*r+3];
        fo.L[8][row * 256 + r] = tf32_rna((a0 + a1) + (a2 + a3));
        fo.L[9][row * 256 + r] = tf32_rna((a0 + a1) - (a2 + a3));
        // branch 5: u5 = rev(a2d), a2d[j] = A2[2j]-A2[2j+1]
        float b0 = A2[1020-4*r], b1 = A2[1021-4*r], b2 = A2[1022-4*r], b3 = A2[1023-4*r];
        fo.L[10][row * 256 + r] = tf32_rna((b2 - b3) + (b0 - b1));
        fo.L[11][row * 256 + r] = tf32_rna((b2 - b3) - (b0 - b1));
        // branch 7: a3v[j] = S2[j]-S2[1023-j]; u7s[r] = a3v[2r]+a3v[2r+1]
        float w0 = S2[2*r]   - S2[1023-2*r];
        float w1 = S2[2*r+1] - S2[1022-2*r];
        fo.L[12][row * 256 + r] = tf32_rna(w0 + w1);
        fo.L[13][row * 256 + r] = tf32_rna(w0 - w1);
        // branch 6: s3v[j] = S2[j]+S2[1023-j]; e6 = s3v[r]+s3v[511-r], o6 = diff
        float e1 = S2[r] + S2[1023-r];
        float e2 = S2[511-r] + S2[512+r];
        fo.L[14][row * 256 + r] = tf32_rna(e1 + e2);
        fo.L[15][row * 256 + r] = tf32_rna(e1 - e2);
    }
}

// ---------------------------------------------------------------- rotate
// Fused 3-level rotation. Per tau < 256, column c:
//   level 3 (d3 = pi(2tau+1)/2048): reconstruct the six 512-vectors at
//   sigma = tau and sigma = 511-tau from 14 leaves (DST-IV via (-1)^sigma).
//   levels 2+1: identical to R11's validated rotate, run for both sigma.
//   br7 rows 8tau+4 / 4092-8tau emitted from P7/Q7 at level 3.
struct RotParams { const float* P[14]; float* out; };

__global__ void __launch_bounds__(256) rotate_kernel(RotParams rp) {
    int tau = blockIdx.y;
    int c = blockIdx.x * 256 + threadIdx.x;          // 0..4095
    size_t off = (size_t)tau * ND + c;
    float c3 = cospif((float)(2 * tau + 1) * (1.0f / 2048.0f));
    float s3 = sinpif((float)(2 * tau + 1) * (1.0f / 2048.0f));
    float sg3 = (tau & 1) ? -1.0f : 1.0f;
    float p0 = rp.P[0][off],  q0 = rp.P[1][off];
    float p1 = rp.P[2][off],  q1 = rp.P[3][off];
    float p2 = rp.P[4][off],  q2 = rp.P[5][off];
    float p3 = rp.P[6][off],  q3 = rp.P[7][off];
    float p4 = rp.P[8][off],  q4 = rp.P[9][off];
    float p5 = rp.P[10][off], q5 = rp.P[11][off];
    float p7 = rp.P[12][off], q7 = rp.P[13][off];
    float* out = rp.out;

    float Scc_a =  c3 * p0 + s3 * q0,  Scc_b = -s3 * p0 + c3 * q0;
    float D1a   =  c3 * p1 + s3 * q1,  D1b   = -s3 * p1 + c3 * q1;
    float Scd_a =  sg3 * D1a,          Scd_b = -sg3 * D1b;
    float Sdc_a =  c3 * p2 + s3 * q2,  Sdc_b = -s3 * p2 + c3 * q2;
    float D3a   =  c3 * p3 + s3 * q3,  D3b   = -s3 * p3 + c3 * q3;
    float Sdd_a =  sg3 * D3a,          Sdd_b = -sg3 * D3b;
    float O2c_a =  c3 * p4 + s3 * q4,  O2c_b = -s3 * p4 + c3 * q4;
    float D5a   =  c3 * p5 + s3 * q5,  D5b   = -s3 * p5 + c3 * q5;
    float O2d_a =  sg3 * D5a,          O2d_b = -sg3 * D5b;
    // branch 7 direct (rows 8*sigma+4)
    out[(size_t)(8 * tau + 4) * ND + c]  =  c3 * p7 + s3 * q7;
    out[(size_t)(4092 - 8 * tau) * ND + c] = -s3 * p7 + c3 * q7;

    #pragma unroll
    for (int h = 0; h < 2; h++) {
        int sg = h ? (511 - tau) : tau;
        float vScc = h ? Scc_b : Scc_a, vScd = h ? Scd_b : Scd_a;
        float vSdc = h ? Sdc_b : Sdc_a, vSdd = h ? Sdd_b : Sdd_a;
        float vO2c = h ? O2c_b : O2c_a, vO2d = h ? O2d_b : O2d_a;
        float c2  = cospif((float)(2 * sg + 1) * (1.0f / 4096.0f));
        float s2  = sinpif((float)(2 * sg + 1) * (1.0f / 4096.0f));
        float c1t = cospif((float)(2 * sg + 1) * (1.0f / 8192.0f));
        float s1t = sinpif((float)(2 * sg + 1) * (1.0f / 8192.0f));
        float c1m = cospif((float)(2047 - 2 * sg) * (1.0f / 8192.0f));
        float s1m = sinpif((float)(2047 - 2 * sg) * (1.0f / 8192.0f));
        float sgn = (sg & 1) ? -1.0f : 1.0f;
        float Sct =  c2 * vScc + s2 * vScd;
        float Scm = -s2 * vScc + c2 * vScd;
        float Drt =  c2 * vSdc + s2 * vSdd;
        float Drm = -s2 * vSdc + c2 * vSdd;
        float Sdt =  sgn * Drt;
        float Sdm = -sgn * Drm;
        out[(size_t)(2 * sg + 1) * ND + c]    =  c1t * Sct + s1t * Sdt;
        out[(size_t)(4095 - 2 * sg) * ND + c] = -s1t * Sct + c1t * Sdt;
        out[(size_t)(2047 - 2 * sg) * ND + c] =  c1m * Scm + s1m * Sdm;
        out[(size_t)(2049 + 2 * sg) * ND + c] = -s1m * Scm + c1m * Sdm;
        out[(size_t)(4 * sg + 2) * ND + c]    =  c2 * vO2c + s2 * vO2d;
        out[(size_t)(4094 - 4 * sg) * ND + c] = -s2 * vO2c + c2 * vO2d;
    }
}

// ---------------------------------------------------------------- GEMM
// 16 uniform branches (M=4096, N=256, K=256), 64 CTAs each:
//   bi 0..13: leaf GEMMs -> P-buffers [256][4096] (stride 1, off 0)
//   bi 14: e6*Cee7 -> out rows 16k;  bi 15: o6*Bc6 -> out rows 16k+8
struct GemmParams {
    const float* A[16];
    const float* B[16];
    float*       O[16];
};

__global__ void __launch_bounds__(256, 2) dct_gemm_kernel(GemmParams p) {
    extern __shared__ __align__(1024) char smem[];
    uint32_t sb = smem_u32(smem);
    int tid = threadIdx.x;
    int wid = tid >> 5, lane = tid & 31;

    int id = blockIdx.x;
    int bi = id >> 6;
    int l  = id & 63;
    int mb = l >> 1, nbe = l & 1;
    int rstride = (bi >= 14) ? 16 : 1;
    int roff    = (bi == 15) ? 8 : 0;
    const float* A = p.A[bi];
    const float* B = p.B[bi];
    float* outT = p.O[bi];

    int crow = tid >> 3, cch = tid & 7;
    const float* Ag = A + (size_t)(mb * BM + crow) * KGEMM + cch * 4;
    const float* Bg = B + (size_t)(nbe * BN + crow) * KGEMM + cch * 4;
    uint32_t sA = swz((uint32_t)(crow * 128 + cch * 16));
    const size_t r32 = (size_t)32 * KGEMM;

    auto issue_stage = [&](int k, int s) {
        uint32_t Ab = sb + s * STAGE_BYTES;
        uint32_t Bb = Ab + BM * 128;
        const float* ga = Ag + k * BK;
        const float* gb = Bg + k * BK;
        #pragma unroll
        for (int t = 0; t < 4; t++) {
            uint32_t so = sA + t * 32 * 128;
            cp16(Ab + so, ga + t * r32);
            cp16(Bb + so, gb + t * r32);
        }
    };

    #pragma unroll
    for (int s = 0; s < STAGES - 1; s++) {
        issue_stage(s, s);
        cp_commit();
    }

    int WM = (wid >> 1) * 32;
    int WN = (wid & 1) * 64;

    float d[2][8][4];
    #pragma unroll
    for (int mt = 0; mt < 2; mt++)
        #pragma unroll
        for (int nt = 0; nt < 8; nt++)
            #pragma unroll
            for (int j = 0; j < 4; j++) d[mt][nt][j] = 0.0f;

    uint32_t aoff = (uint32_t)((lane & 15) * 128 + (lane >> 4) * 16);
    uint32_t boff = (uint32_t)(((lane & 7) + ((lane >> 4) << 3)) * 128
                               + ((lane >> 3) & 1) * 16);

    int s = 0;
    for (int k = 0; k < KIT; k++) {
        cp_wait<STAGES - 2>();
        __syncthreads();
        if (k + STAGES - 1 < KIT)
            issue_stage(k + STAGES - 1, (k + STAGES - 1) % STAGES);
        cp_commit();

        uint32_t Ab = sb + s * STAGE_BYTES;
        uint32_t Bb = Ab + BM * 128;

        #pragma unroll
        for (int ks = 0; ks < 4; ks++) {
            uint32_t a0[4], a1r[4], bfr[2][4];
            ldsm4(a0,  Ab + swz((uint32_t)(WM * 128)        + aoff + ks * 32));
            ldsm4(a1r, Ab + swz((uint32_t)((WM + 16) * 128) + aoff + ks * 32));
            ldsm4(bfr[0], Bb + swz((uint32_t)(WN * 128)        + boff + ks * 32));
            ldsm4(bfr[1], Bb + swz((uint32_t)((WN + 16) * 128) + boff + ks * 32));
            #pragma unroll
            for (int nt = 0; nt < 4; nt++) {
                const uint32_t* bb = &bfr[nt >> 1][(nt & 1) * 2];
                mma1688(d[0][nt], a0, bb);
                mma1688(d[1][nt], a1r, bb);
            }
            ldsm4(bfr[0], Bb + swz((uint32_t)((WN + 32) * 128) + boff + ks * 32));
            ldsm4(bfr[1], Bb + swz((uint32_t)((WN + 48) * 128) + boff + ks * 32));
            #pragma unroll
            for (int nt = 0; nt < 4; nt++) {
                const uint32_t* bb = &bfr[nt >> 1][(nt & 1) * 2];
                mma1688(d[0][nt + 4], a0, bb);
                mma1688(d[1][nt + 4], a1r, bb);
            }
        }
        s = (s == STAGES - 1) ? 0 : s + 1;
    }

    // epilogue: transpose through SMEM, coalesced float4 stores
    cp_wait<0>();
    __syncthreads();
    float* T = (float*)smem;
    int g = lane >> 2, tig = lane & 3;
    #pragma unroll
    for (int mt = 0; mt < 2; mt++) {
        #pragma unroll
        for (int nt = 0; nt < 8; nt++) {
            int m = WM + mt * 16 + g;
            int n = WN + nt * 8 + 2 * tig;
            T[n * 132 + m]           = d[mt][nt][0];
            T[(n + 1) * 132 + m]     = d[mt][nt][1];
            T[n * 132 + m + 8]       = d[mt][nt][2];
            T[(n + 1) * 132 + m + 8] = d[mt][nt][3];
        }
    }
    __syncthreads();
    #pragma unroll
    for (int it = 0; it < 16; it++) {
        int i = tid + it * 256;
        int r = i >> 5, c = (i & 31) * 4;
        float4 v = *(float4*)&T[r * 132 + c];
        size_t orow = (size_t)(rstride * (nbe * BN + r) + roff);
        *(float4*)&outT[orow * ND + mb * BM + c] = v;
    }
}

// ---------------------------------------------------------------- host
extern "C" void kernel_launch(void* const* d_in, const int* in_sizes, int n_in,
                              void* d_out, int out_size) {
    void *pBc6, *pBs6, *pCee7, *pYt;
    void *pL[16], *pP[14];
    cudaGetSymbolAddress(&pBc6,  g_Bc6);
    cudaGetSymbolAddress(&pBs6,  g_Bs6);
    cudaGetSymbolAddress(&pCee7, g_Cee7);
    cudaGetSymbolAddress(&pYt,   g_Yt);
    {
        void* base;
        cudaGetSymbolAddress(&base, g_L);
        for (int i = 0; i < 16; i++)
            pL[i] = (char*)base + (size_t)i * ND * 256 * sizeof(float);
        cudaGetSymbolAddress(&base, g_P);
        for (int i = 0; i < 14; i++)
            pP[i] = (char*)base + (size_t)i * 256 * ND * sizeof(float);
    }

    gen_b6_kernel<<<dim3(1, 256), 64>>>((float4*)pBc6, (float4*)pBs6);
    gen_cee7_kernel<<<dim3(1, 256), 64>>>((float4*)pCee7);

    cudaFuncSetAttribute(dct_gemm_kernel,
                         cudaFuncAttributeMaxDynamicSharedMemorySize, SMEM_TOTAL);

    FoldOut fo;
    for (int i = 0; i < 16; i++) fo.L[i] = (float*)pL[i];

    GemmParams gp;
    for (int i = 0; i < 16; i++) {
        gp.A[i] = (const float*)pL[i];
        gp.B[i] = (i == 14) ? (const float*)pCee7
                : (i == 15) ? (const float*)pBc6
                : ((i & 1) ? (const float*)pBs6 : (const float*)pBc6);
        if (i < 14) gp.O[i] = (float*)pP[i];
    }

    RotParams rp;
    for (int i = 0; i < 14; i++) rp.P[i] = (const float*)pP[i];

    // ---- Pass A: x -> Yt[v][i]
    fold_kernel<<<ND, 256>>>((const float*)d_in[0], fo);
    gp.O[14] = (float*)pYt;  gp.O[15] = (float*)pYt;
    dct_gemm_kernel<<<1024, 256, SMEM_TOTAL>>>(gp);
    rp.out = (float*)pYt;
    rotate_kernel<<<dim3(16, 256), 256>>>(rp);

    // ---- Pass B: Yt -> out[u][v]
    fold_kernel<<<ND, 256>>>((const float*)pYt, fo);
    gp.O[14] = (float*)d_out;  gp.O[15] = (float*)d_out;
    dct_gemm_kernel<<<1024, 256, SMEM_TOTAL>>>(gp);
    rp.out = (float*)d_out;
    rotate_kernel<<<dim3(16, 256), 256>>>(rp);
}